// round 1
// baseline (speedup 1.0000x reference)
#include <cuda_runtime.h>
#include <cstdint>

#define NN    1024
#define DDIM  512
#define HDIM  150
#define HP    160
#define WWIN  250
#define OUTW  251
#define PAIRS 64
#define DK    32
#define NTHR  256

typedef unsigned long long u64;

__device__ __forceinline__ u64 pack2(float a, float b) {
    u64 r; asm("mov.b64 %0, {%1, %2};" : "=l"(r) : "f"(a), "f"(b)); return r;
}
__device__ __forceinline__ void unpack2(u64 v, float& a, float& b) {
    asm("mov.b64 {%0, %1}, %2;" : "=f"(a), "=f"(b) : "l"(v));
}
__device__ __forceinline__ u64 fma2(u64 a, u64 b, u64 c) {
    u64 d; asm("fma.rn.f32x2 %0, %1, %2, %3;" : "=l"(d) : "l"(a), "l"(b), "l"(c)); return d;
}

// Scratch: giT = g@W1a + b1, gjT = g@W1b, both padded to HP cols (zeros past HDIM).
__device__ float g_giT[NN * HP];
__device__ float g_gjT[NN * HP];

// ---------------------------------------------------------------------------
// Precompute kernel: 8 rows of g per block, 160 "h" threads (10 idle past 150).
// ---------------------------------------------------------------------------
__global__ void __launch_bounds__(256) precompute_kernel(
    const float* __restrict__ g, const float* __restrict__ W1,
    const float* __restrict__ b1)
{
    __shared__ float gs[8 * DDIM];
    const int i0 = blockIdx.x * 8;
    const int tid = threadIdx.x;

    #pragma unroll
    for (int e = 0; e < (8 * DDIM) / 256; ++e) {
        int idx = tid + e * 256;
        gs[idx] = g[i0 * DDIM + idx];
    }
    __syncthreads();

    if (tid < HP) {
        const int h = tid;
        const bool hv = (h < HDIM);
        float acc1[8], acc2[8];
        float bb = hv ? b1[h] : 0.f;
        #pragma unroll
        for (int q = 0; q < 8; ++q) { acc1[q] = bb; acc2[q] = 0.f; }
        const float* W1b = W1 + DDIM * HDIM;
        for (int d = 0; d < DDIM; ++d) {
            float w1 = hv ? W1[d * HDIM + h]  : 0.f;
            float w2 = hv ? W1b[d * HDIM + h] : 0.f;
            #pragma unroll
            for (int q = 0; q < 8; ++q) {
                float gv = gs[q * DDIM + d];
                acc1[q] += gv * w1;
                acc2[q] += gv * w2;
            }
        }
        #pragma unroll
        for (int q = 0; q < 8; ++q) {
            g_giT[(i0 + q) * HP + h] = acc1[q];
            g_gjT[(i0 + q) * HP + h] = acc2[q];
        }
    }
}

// ---------------------------------------------------------------------------
// Main pair kernel: CTA = (i, 64 consecutive k). Thread tile: 4 pairs x 10 h.
// SMEM: sW[32][160] | sH1[64][161] (sGJ[64][33] aliases sH1) | gis[32]
// ---------------------------------------------------------------------------
#define SMEM_FLOATS (DK * HP + PAIRS * 161 + DK)

__global__ void __launch_bounds__(NTHR) pair_kernel(
    const float* __restrict__ g,  const float* __restrict__ sm,
    const float* __restrict__ W1, const float* __restrict__ W2,
    const float* __restrict__ b2, const float* __restrict__ W3,
    const float* __restrict__ b3, float* __restrict__ out)
{
    extern __shared__ float smem[];
    float* sW  = smem;                   // DK*HP
    float* sH1 = smem + DK * HP;         // PAIRS*161
    float* sGJ = sH1;                    // PAIRS*33 (aliases sH1, dead before h1 written)
    float* gis = smem + DK * HP + PAIRS * 161;  // DK

    const int i   = blockIdx.y;
    const int k0  = blockIdx.x * PAIRS;
    const int tid = threadIdx.x;
    const int tp  = tid & 15;
    const int th  = tid >> 4;
    const int pbase = tp * 4;
    const int hbase = th * 10;

    const float* gi_row = g + i * DDIM;
    const float* W1c = W1 + 2 * DDIM * HDIM;

    int jcl[4];
    #pragma unroll
    for (int q = 0; q < 4; ++q) {
        int j = i - WWIN + k0 + pbase + q;
        jcl[q] = min(max(j, 0), NN - 1);
    }

    // ---------------- Stage 1: h1 = relu(giT + gjT + (gi*gj)@W1c) -----------
    u64 acc[4][5];
    #pragma unroll
    for (int q = 0; q < 4; ++q)
        #pragma unroll
        for (int v = 0; v < 5; ++v) acc[q][v] = 0ull;

    for (int t = 0; t < DDIM / DK; ++t) {
        const int d0 = t * DK;
        // W1c tile -> sW (zero-pad h >= 150)
        #pragma unroll
        for (int e = 0; e < (DK * HP) / NTHR; ++e) {
            int idx = tid + e * NTHR;
            int dd = idx / HP;
            int h  = idx - dd * HP;
            sW[idx] = (h < HDIM) ? W1c[(d0 + dd) * HDIM + h] : 0.f;
        }
        // g_j tile -> sGJ[p][dd] (pitch 33)
        #pragma unroll
        for (int e = 0; e < (DK * PAIRS) / NTHR; ++e) {
            int idx = tid + e * NTHR;
            int dd = idx & (DK - 1);
            int p  = idx >> 5;
            int jc = min(max(i - WWIN + k0 + p, 0), NN - 1);
            sGJ[p * 33 + dd] = g[jc * DDIM + d0 + dd];
        }
        if (tid < DK) gis[tid] = gi_row[d0 + tid];
        __syncthreads();

        #pragma unroll 8
        for (int dd = 0; dd < DK; ++dd) {
            float gv = gis[dd];
            u64 a2[4];
            #pragma unroll
            for (int q = 0; q < 4; ++q) {
                float a = gv * sGJ[(pbase + q) * 33 + dd];
                a2[q] = pack2(a, a);
            }
            const float* wrow = sW + dd * HP + hbase;
            #pragma unroll
            for (int v = 0; v < 5; ++v) {
                u64 w = *reinterpret_cast<const u64*>(wrow + 2 * v);
                #pragma unroll
                for (int q = 0; q < 4; ++q) acc[q][v] = fma2(a2[q], w, acc[q][v]);
            }
        }
        __syncthreads();
    }

    // Combine with precomputed terms, relu, store h1 to SMEM [pair][161]
    {
        const float* giRow = g_giT + i * HP;
        #pragma unroll
        for (int q = 0; q < 4; ++q) {
            const float* gjRow = g_gjT + jcl[q] * HP;
            float* hrow = sH1 + (pbase + q) * 161;
            #pragma unroll
            for (int v = 0; v < 5; ++v) {
                float f0, f1; unpack2(acc[q][v], f0, f1);
                int h = hbase + 2 * v;
                float x0 = f0 + giRow[h]     + gjRow[h];
                float x1 = f1 + giRow[h + 1] + gjRow[h + 1];
                hrow[h]     = fmaxf(x0, 0.f);
                hrow[h + 1] = fmaxf(x1, 0.f);
            }
        }
    }
    __syncthreads();

    // ---------------- Stage 2: h2 = relu(h1 @ W2 + b2) ----------------------
    u64 acc2[4][5];
    #pragma unroll
    for (int q = 0; q < 4; ++q)
        #pragma unroll
        for (int v = 0; v < 5; ++v) acc2[q][v] = 0ull;

    for (int t2 = 0; t2 < HP / DK; ++t2) {
        const int c0 = t2 * DK;
        #pragma unroll
        for (int e = 0; e < (DK * HP) / NTHR; ++e) {
            int idx = tid + e * NTHR;
            int dd = idx / HP;
            int h  = idx - dd * HP;
            int r  = c0 + dd;
            sW[idx] = (r < HDIM && h < HDIM) ? W2[r * HDIM + h] : 0.f;
        }
        __syncthreads();

        #pragma unroll 8
        for (int dd = 0; dd < DK; ++dd) {
            u64 a2[4];
            #pragma unroll
            for (int q = 0; q < 4; ++q) {
                float a = sH1[(pbase + q) * 161 + c0 + dd];
                a2[q] = pack2(a, a);
            }
            const float* wrow = sW + dd * HP + hbase;
            #pragma unroll
            for (int v = 0; v < 5; ++v) {
                u64 w = *reinterpret_cast<const u64*>(wrow + 2 * v);
                #pragma unroll
                for (int q = 0; q < 4; ++q) acc2[q][v] = fma2(a2[q], w, acc2[q][v]);
            }
        }
        __syncthreads();
    }

    // ---------------- Epilogue: s = relu(h2+b2) @ W3, reduce, write ---------
    float spart[4] = {0.f, 0.f, 0.f, 0.f};
    #pragma unroll
    for (int v = 0; v < 5; ++v) {
        int h = hbase + 2 * v;
        float b2a = (h     < HDIM) ? b2[h]     : 0.f;
        float b2b = (h + 1 < HDIM) ? b2[h + 1] : 0.f;
        float w3a = (h     < HDIM) ? W3[h]     : 0.f;
        float w3b = (h + 1 < HDIM) ? W3[h + 1] : 0.f;
        #pragma unroll
        for (int q = 0; q < 4; ++q) {
            float f0, f1; unpack2(acc2[q][v], f0, f1);
            spart[q] += fmaxf(f0 + b2a, 0.f) * w3a + fmaxf(f1 + b2b, 0.f) * w3b;
        }
    }

    float* sred = smem;  // alias sW (done with it; sync above guarantees safety)
    #pragma unroll
    for (int q = 0; q < 4; ++q) sred[th * PAIRS + pbase + q] = spart[q];
    __syncthreads();

    if (tid < PAIRS) {
        const int p = tid;
        float s = 0.f;
        #pragma unroll
        for (int r = 0; r < 16; ++r) s += sred[r * PAIRS + p];
        int k = k0 + p;
        int j = i - WWIN + k;
        if (k < WWIN) {
            float val = 0.f;
            if (j >= 0) val = s + b3[0] + sm[i] + sm[j];
            out[i * OUTW + k] = val;
        } else if (k == WWIN) {
            out[i * OUTW + k] = 0.f;   // trailing epsilon column
        }
    }
}

// ---------------------------------------------------------------------------
extern "C" void kernel_launch(void* const* d_in, const int* in_sizes, int n_in,
                              void* d_out, int out_size)
{
    const float* g  = (const float*)d_in[0];
    const float* sm = (const float*)d_in[1];
    const float* W1 = (const float*)d_in[2];
    const float* b1 = (const float*)d_in[3];
    const float* W2 = (const float*)d_in[4];
    const float* b2 = (const float*)d_in[5];
    const float* W3 = (const float*)d_in[6];
    const float* b3 = (const float*)d_in[7];
    float* out = (float*)d_out;

    const int smem_bytes = SMEM_FLOATS * (int)sizeof(float);
    cudaFuncSetAttribute(pair_kernel, cudaFuncAttributeMaxDynamicSharedMemorySize,
                         smem_bytes);

    precompute_kernel<<<NN / 8, 256>>>(g, W1, b1);

    dim3 grid((WWIN + PAIRS - 1) / PAIRS, NN);   // 4 x 1024 (k up to 255; guarded)
    pair_kernel<<<grid, NTHR, smem_bytes>>>(g, sm, W1, W2, b2, W3, b3, out);
}

// round 3
// speedup vs baseline: 2.1259x; 2.1259x over previous
#include <cuda_runtime.h>
#include <cuda_fp16.h>
#include <cstdint>

#define NN    1024
#define DDIM  512
#define HDIM  150
#define HP    160
#define WWIN  250
#define OUTW  251
#define NTHR  256

// ---- dynamic SMEM byte offsets ----
#define A1HI  0          // 128x72 halves = 18432 B   (stage1 A hi)
#define A1LO  18432      // stage1 A lo
#define BHI   36864      // 160x72 halves = 23040 B   (stage1 B hi)
#define BLO   59904      // stage1 B lo
// stage2 aliases: h1 tiles (single fp16) at 0 / 18432 / 36864 ; B2 at 59904 / 82944
#define B2HI  59904
#define B2LO  82944
#define SRED  105984     // 128 floats
#define SMEM_TOTAL 107520

#define TILE_W_HALVES 11520     // 160*72
#define TILE_W_U4     1440      // 23040 B / 16

// ---------------------------------------------------------------------------
// Device scratch
// ---------------------------------------------------------------------------
__device__ float g_giT[NN * HP];      // g@W1a + b1, [i][h], zero pad h>=150
__device__ float g_gjT_T[HP * NN];    // (g@W1b)^T, [h][i], zero pad
__device__ __align__(16) __half g_W1hi[8 * TILE_W_HALVES];
__device__ __align__(16) __half g_W1lo[8 * TILE_W_HALVES];
__device__ __align__(16) __half g_W2hi[3 * TILE_W_HALVES];
__device__ __align__(16) __half g_W2lo[3 * TILE_W_HALVES];

// ---------------------------------------------------------------------------
// Helpers
// ---------------------------------------------------------------------------
__device__ __forceinline__ void mma16816(float* c,
    uint32_t a0, uint32_t a1, uint32_t a2, uint32_t a3,
    uint32_t b0, uint32_t b1)
{
    asm volatile(
        "mma.sync.aligned.m16n8k16.row.col.f32.f16.f16.f32 "
        "{%0,%1,%2,%3}, {%4,%5,%6,%7}, {%8,%9}, {%0,%1,%2,%3};"
        : "+f"(c[0]), "+f"(c[1]), "+f"(c[2]), "+f"(c[3])
        : "r"(a0), "r"(a1), "r"(a2), "r"(a3), "r"(b0), "r"(b1));
}

__device__ __forceinline__ void split_h2(float v0, float v1,
                                         uint32_t& hi, uint32_t& lo)
{
    __half2 h = __float22half2_rn(make_float2(v0, v1));
    float r0 = v0 - __low2float(h);
    float r1 = v1 - __high2float(h);
    __half2 l = __float22half2_rn(make_float2(r0, r1));
    hi = *(uint32_t*)&h;
    lo = *(uint32_t*)&l;
}

// ---------------------------------------------------------------------------
// Precompute 1: giT = g@W1a + b1 (row-major), gjT_T = (g@W1b)^T  (fp32 exact)
// ---------------------------------------------------------------------------
__global__ void __launch_bounds__(256) precompute_gt(
    const float* __restrict__ g, const float* __restrict__ W1,
    const float* __restrict__ b1)
{
    __shared__ float gs[8 * DDIM];
    const int i0 = blockIdx.x * 8;
    const int tid = threadIdx.x;
    #pragma unroll
    for (int e = 0; e < (8 * DDIM) / 256; ++e) {
        int idx = tid + e * 256;
        gs[idx] = g[i0 * DDIM + idx];
    }
    __syncthreads();
    if (tid < HP) {
        const int h = tid;
        const bool hv = (h < HDIM);
        float acc1[8], acc2[8];
        float bb = hv ? b1[h] : 0.f;
        #pragma unroll
        for (int q = 0; q < 8; ++q) { acc1[q] = bb; acc2[q] = 0.f; }
        const float* W1b = W1 + DDIM * HDIM;
        for (int d = 0; d < DDIM; ++d) {
            float w1 = hv ? W1[d * HDIM + h]  : 0.f;
            float w2 = hv ? W1b[d * HDIM + h] : 0.f;
            #pragma unroll
            for (int q = 0; q < 8; ++q) {
                float gv = gs[q * DDIM + d];
                acc1[q] += gv * w1;
                acc2[q] += gv * w2;
            }
        }
        #pragma unroll
        for (int q = 0; q < 8; ++q) {
            g_giT[(i0 + q) * HP + h]   = acc1[q];
            g_gjT_T[h * NN + (i0 + q)] = acc2[q];
        }
    }
}

// ---------------------------------------------------------------------------
// Precompute 2: split W1c / W2 into fp16 hi/lo B-tiles [n=0..159][k=0..63],
// pitch 72 halves (144B rows), zero-padded. Block bt: 0..7 = W1c kt, 8..10 = W2.
// ---------------------------------------------------------------------------
__global__ void __launch_bounds__(256) precompute_wsplit(
    const float* __restrict__ W1, const float* __restrict__ W2)
{
    const int bt = blockIdx.x;
    const int tid = threadIdx.x;
    const float* W1c = W1 + 2 * DDIM * HDIM;
    __half *dhi, *dlo;
    int kt;
    if (bt < 8) { kt = bt; dhi = g_W1hi + kt * TILE_W_HALVES; dlo = g_W1lo + kt * TILE_W_HALVES; }
    else        { kt = bt - 8; dhi = g_W2hi + kt * TILE_W_HALVES; dlo = g_W2lo + kt * TILE_W_HALVES; }

    for (int idx = tid; idx < HP * 64; idx += 256) {
        int n = idx >> 6;           // output-h row
        int k = idx & 63;           // k within tile
        float val;
        if (bt < 8) {
            int d = kt * 64 + k;
            val = (n < HDIM) ? W1c[d * HDIM + n] : 0.f;
        } else {
            int kg = kt * 64 + k;
            val = (kg < HDIM && n < HDIM) ? W2[kg * HDIM + n] : 0.f;
        }
        __half h = __float2half_rn(val);
        __half l = __float2half_rn(val - __half2float(h));
        dhi[n * 72 + k] = h;
        dlo[n * 72 + k] = l;
    }
}

// ---------------------------------------------------------------------------
// Main kernel. CTA = (i, 128 pairs). grid (2, 1024). 8 warps: wm=wid&3 (M 32),
// wn=wid>>2 (N 80). Warp tile 32x80 = 2 m16-tiles x 10 n8-tiles.
// ---------------------------------------------------------------------------
__global__ void __launch_bounds__(NTHR, 2) pair_mma_kernel(
    const float* __restrict__ g,  const float* __restrict__ sm,
    const float* __restrict__ b2, const float* __restrict__ W3,
    const float* __restrict__ b3, float* __restrict__ out)
{
    extern __shared__ char smem[];
    const int tid = threadIdx.x;
    const int wid = tid >> 5, lid = tid & 31;
    const int wm = wid & 3, wn = wid >> 2;
    const int gq = lid >> 2, t = lid & 3;     // quad row / quad lane
    const int i  = blockIdx.y;
    const int k0 = blockIdx.x * 128;

    // clamped antecedent rows for this thread's 4 accumulator row-groups
    int jrow[2][2];
    #pragma unroll
    for (int mi = 0; mi < 2; ++mi)
        #pragma unroll
        for (int h8 = 0; h8 < 2; ++h8) {
            int p = wm * 32 + mi * 16 + gq + h8 * 8;
            int j = i - WWIN + k0 + p;
            jrow[mi][h8] = min(max(j, 0), NN - 1);
        }

    // ---- accumulators, init with bias terms giT[i][col] + gjT[col][j] ----
    float acc[2][10][4];
    {
        const float* giR = g_giT + i * HP;
        #pragma unroll
        for (int nt = 0; nt < 10; ++nt)
            #pragma unroll
            for (int par = 0; par < 2; ++par) {
                int col = wn * 80 + nt * 8 + 2 * t + par;
                float gic = giR[col];
                const float* gjc = g_gjT_T + col * NN;
                #pragma unroll
                for (int mi = 0; mi < 2; ++mi)
                    #pragma unroll
                    for (int h8 = 0; h8 < 2; ++h8)
                        acc[mi][nt][h8 * 2 + par] = gic + gjc[jrow[mi][h8]];
            }
    }

    const uint32_t a_off = (uint32_t)(((wm * 32 + gq) * 36 + t) * 4);
    const uint32_t b_off = (uint32_t)(((wn * 80 + gq) * 36 + t) * 4);

    // =================== Stage 1: acc += (gi*gj) @ W1c ====================
    const int pA = tid >> 1;          // A-prep row 0..127
    const int sA = tid & 1;           // which 32-col half
    const int jA = min(max(i - WWIN + k0 + pA, 0), NN - 1);
    const float4* giRow4 = (const float4*)(g + i * DDIM);
    const float4* gjRow4 = (const float4*)(g + jA * DDIM);

    for (int kt = 0; kt < 8; ++kt) {
        // --- A prep: products -> split fp16 hi/lo ---
        {
            const int qb = kt * 16 + sA * 8;          // float4 index base
            char* dsthi = smem + A1HI + pA * 144 + sA * 64;
            char* dstlo = smem + A1LO + pA * 144 + sA * 64;
            #pragma unroll
            for (int q = 0; q < 8; ++q) {
                float4 a = giRow4[qb + q];
                float4 b = gjRow4[qb + q];
                float v0 = a.x * b.x, v1 = a.y * b.y, v2 = a.z * b.z, v3 = a.w * b.w;
                uint32_t h0, l0, h1, l1;
                split_h2(v0, v1, h0, l0);
                split_h2(v2, v3, h1, l1);
                *(uint2*)(dsthi + q * 8) = make_uint2(h0, h1);
                *(uint2*)(dstlo + q * 8) = make_uint2(l0, l1);
            }
        }
        // --- B tiles copy ---
        {
            const uint4* shi = (const uint4*)(g_W1hi + kt * TILE_W_HALVES);
            const uint4* slo = (const uint4*)(g_W1lo + kt * TILE_W_HALVES);
            uint4* dhi = (uint4*)(smem + BHI);
            uint4* dlo = (uint4*)(smem + BLO);
            for (int x = tid; x < TILE_W_U4; x += NTHR) { dhi[x] = shi[x]; dlo[x] = slo[x]; }
        }
        __syncthreads();

        #pragma unroll
        for (int ks = 0; ks < 4; ++ks) {
            const uint32_t ko = ks * 32;
            uint32_t ah[2][4], al[2][4];
            #pragma unroll
            for (int mi = 0; mi < 2; ++mi) {
                uint32_t base = a_off + mi * 2304 + ko;
                ah[mi][0] = *(const uint32_t*)(smem + A1HI + base);
                ah[mi][1] = *(const uint32_t*)(smem + A1HI + base + 1152);
                ah[mi][2] = *(const uint32_t*)(smem + A1HI + base + 16);
                ah[mi][3] = *(const uint32_t*)(smem + A1HI + base + 1168);
                al[mi][0] = *(const uint32_t*)(smem + A1LO + base);
                al[mi][1] = *(const uint32_t*)(smem + A1LO + base + 1152);
                al[mi][2] = *(const uint32_t*)(smem + A1LO + base + 16);
                al[mi][3] = *(const uint32_t*)(smem + A1LO + base + 1168);
            }
            #pragma unroll
            for (int nt = 0; nt < 10; ++nt) {
                uint32_t bb = b_off + nt * 1152 + ko;
                uint32_t bh0 = *(const uint32_t*)(smem + BHI + bb);
                uint32_t bh1 = *(const uint32_t*)(smem + BHI + bb + 16);
                #pragma unroll
                for (int mi = 0; mi < 2; ++mi) {
                    mma16816(acc[mi][nt], ah[mi][0], ah[mi][1], ah[mi][2], ah[mi][3], bh0, bh1);
                    mma16816(acc[mi][nt], al[mi][0], al[mi][1], al[mi][2], al[mi][3], bh0, bh1);
                }
                uint32_t bl0 = *(const uint32_t*)(smem + BLO + bb);
                uint32_t bl1 = *(const uint32_t*)(smem + BLO + bb + 16);
                #pragma unroll
                for (int mi = 0; mi < 2; ++mi)
                    mma16816(acc[mi][nt], ah[mi][0], ah[mi][1], ah[mi][2], ah[mi][3], bl0, bl1);
            }
        }
        __syncthreads();
    }

    // ============ h1 = relu(acc) -> SMEM (single fp16, 3 k-tiles) ==========
    // tile bases: kt2=0 -> 0, kt2=1 -> 18432, kt2=2 -> 36864
    {
        #pragma unroll
        for (int mi = 0; mi < 2; ++mi)
            #pragma unroll
            for (int h8 = 0; h8 < 2; ++h8) {
                int row = wm * 32 + mi * 16 + gq + h8 * 8;
                #pragma unroll
                for (int nt = 0; nt < 10; ++nt) {
                    int col = wn * 80 + nt * 8 + 2 * t;
                    float v0 = fmaxf(acc[mi][nt][h8 * 2 + 0], 0.f);
                    float v1 = fmaxf(acc[mi][nt][h8 * 2 + 1], 0.f);
                    __half2 h = __float22half2_rn(make_float2(v0, v1));
                    int tile = col >> 6;
                    uint32_t off = (uint32_t)(tile * 18432 + row * 144 + (col & 63) * 2);
                    *(uint32_t*)(smem + off) = *(uint32_t*)&h;
                }
            }
        // zero-fill tile2 cols 160..191 (halves 32..63)
        for (int idx = tid; idx < 128 * 16; idx += NTHR) {
            int row = idx >> 4, w = idx & 15;
            *(uint32_t*)(smem + 36864 + row * 144 + 64 + w * 4) = 0u;
        }
    }

    // ---- re-init acc with b2 for stage 2 ----
    #pragma unroll
    for (int nt = 0; nt < 10; ++nt)
        #pragma unroll
        for (int par = 0; par < 2; ++par) {
            int col = wn * 80 + nt * 8 + 2 * t + par;
            float bv = (col < HDIM) ? b2[col] : 0.f;
            #pragma unroll
            for (int mi = 0; mi < 2; ++mi)
                #pragma unroll
                for (int h8 = 0; h8 < 2; ++h8)
                    acc[mi][nt][h8 * 2 + par] = bv;
        }

    // =================== Stage 2: acc += relu(h1) @ W2 =====================
    for (int kt2 = 0; kt2 < 3; ++kt2) {
        {
            const uint4* shi = (const uint4*)(g_W2hi + kt2 * TILE_W_HALVES);
            const uint4* slo = (const uint4*)(g_W2lo + kt2 * TILE_W_HALVES);
            uint4* dhi = (uint4*)(smem + B2HI);
            uint4* dlo = (uint4*)(smem + B2LO);
            for (int x = tid; x < TILE_W_U4; x += NTHR) { dhi[x] = shi[x]; dlo[x] = slo[x]; }
        }
        __syncthreads();
        const uint32_t tbase = (uint32_t)(kt2 * 18432);
        #pragma unroll
        for (int ks = 0; ks < 4; ++ks) {
            const uint32_t ko = ks * 32;
            uint32_t af[2][4];
            #pragma unroll
            for (int mi = 0; mi < 2; ++mi) {
                uint32_t base = tbase + a_off + mi * 2304 + ko;
                af[mi][0] = *(const uint32_t*)(smem + base);
                af[mi][1] = *(const uint32_t*)(smem + base + 1152);
                af[mi][2] = *(const uint32_t*)(smem + base + 16);
                af[mi][3] = *(const uint32_t*)(smem + base + 1168);
            }
            #pragma unroll
            for (int nt = 0; nt < 10; ++nt) {
                uint32_t bb = b_off + nt * 1152 + ko;
                uint32_t bh0 = *(const uint32_t*)(smem + B2HI + bb);
                uint32_t bh1 = *(const uint32_t*)(smem + B2HI + bb + 16);
                uint32_t bl0 = *(const uint32_t*)(smem + B2LO + bb);
                uint32_t bl1 = *(const uint32_t*)(smem + B2LO + bb + 16);
                #pragma unroll
                for (int mi = 0; mi < 2; ++mi) {
                    mma16816(acc[mi][nt], af[mi][0], af[mi][1], af[mi][2], af[mi][3], bh0, bh1);
                    mma16816(acc[mi][nt], af[mi][0], af[mi][1], af[mi][2], af[mi][3], bl0, bl1);
                }
            }
        }
        __syncthreads();
    }

    // =================== Epilogue: relu(acc) @ W3, reduce ==================
    float rsum[2][2] = {{0.f, 0.f}, {0.f, 0.f}};
    #pragma unroll
    for (int nt = 0; nt < 10; ++nt)
        #pragma unroll
        for (int par = 0; par < 2; ++par) {
            int col = wn * 80 + nt * 8 + 2 * t + par;
            float w3 = (col < HDIM) ? W3[col] : 0.f;
            #pragma unroll
            for (int mi = 0; mi < 2; ++mi)
                #pragma unroll
                for (int h8 = 0; h8 < 2; ++h8)
                    rsum[mi][h8] += fmaxf(acc[mi][nt][h8 * 2 + par], 0.f) * w3;
        }
    #pragma unroll
    for (int mi = 0; mi < 2; ++mi)
        #pragma unroll
        for (int h8 = 0; h8 < 2; ++h8) {
            float v = rsum[mi][h8];
            v += __shfl_xor_sync(0xffffffffu, v, 1);
            v += __shfl_xor_sync(0xffffffffu, v, 2);
            rsum[mi][h8] = v;
        }

    float* sred = (float*)(smem + SRED);
    if (wn == 0 && t == 0) {
        #pragma unroll
        for (int mi = 0; mi < 2; ++mi)
            #pragma unroll
            for (int h8 = 0; h8 < 2; ++h8)
                sred[wm * 32 + mi * 16 + gq + h8 * 8] = rsum[mi][h8];
    }
    __syncthreads();
    if (wn == 1 && t == 0) {
        float smi = sm[i];
        float bb3 = b3[0];
        #pragma unroll
        for (int mi = 0; mi < 2; ++mi)
            #pragma unroll
            for (int h8 = 0; h8 < 2; ++h8) {
                int p = wm * 32 + mi * 16 + gq + h8 * 8;
                int k = k0 + p;
                int j = i - WWIN + k;
                float tot = rsum[mi][h8] + sred[p];
                if (k < WWIN) {
                    float val = 0.f;
                    if (j >= 0) val = tot + bb3 + smi + sm[j];
                    out[i * OUTW + k] = val;
                } else if (k == WWIN) {
                    out[i * OUTW + k] = 0.f;   // epsilon column
                }
            }
    }
}

// ---------------------------------------------------------------------------
extern "C" void kernel_launch(void* const* d_in, const int* in_sizes, int n_in,
                              void* d_out, int out_size)
{
    const float* g  = (const float*)d_in[0];
    const float* sm = (const float*)d_in[1];
    const float* W1 = (const float*)d_in[2];
    const float* b1 = (const float*)d_in[3];
    const float* W2 = (const float*)d_in[4];
    const float* b2 = (const float*)d_in[5];
    const float* W3 = (const float*)d_in[6];
    const float* b3 = (const float*)d_in[7];
    float* out = (float*)d_out;

    cudaFuncSetAttribute(pair_mma_kernel,
                         cudaFuncAttributeMaxDynamicSharedMemorySize, SMEM_TOTAL);

    precompute_gt<<<NN / 8, 256>>>(g, W1, b1);
    precompute_wsplit<<<11, 256>>>(W1, W2);

    dim3 grid(2, NN);
    pair_mma_kernel<<<grid, NTHR, SMEM_TOTAL>>>(g, sm, b2, W3, b3, out);
}

// round 4
// speedup vs baseline: 3.0688x; 1.4436x over previous
#include <cuda_runtime.h>
#include <cuda_fp16.h>
#include <cstdint>

#define NN    1024
#define DDIM  512
#define HDIM  150
#define HP    160
#define WWIN  250
#define OUTW  251
#define NTHR  256

// ---- dynamic SMEM byte offsets ----
#define A1HI  0          // 128x72 halves = 18432 B   (stage1 A hi)
#define A1LO  18432      // stage1 A lo
#define BHI   36864      // 160x72 halves = 23040 B   (stage1 B hi; no lo needed)
// stage2 aliases: h1 tiles (single fp16) at 0 / 18432 / 36864 ; B2 at 59904 / 82944
#define B2HI  59904
#define B2LO  82944
#define SRED  105984     // 128 floats
#define SMEM_TOTAL 107520

#define TILE_W_HALVES 11520     // 160*72
#define TILE_W_U4     1440      // 23040 B / 16

// ---------------------------------------------------------------------------
// Device scratch
// ---------------------------------------------------------------------------
__device__ float g_giT[NN * HP];      // g@W1a + b1, [i][h], zero pad h>=150
__device__ float g_gjT_T[HP * NN];    // (g@W1b)^T, [h][i], zero pad
__device__ __align__(16) __half g_W1hi[8 * TILE_W_HALVES];
__device__ __align__(16) __half g_W2hi[3 * TILE_W_HALVES];
__device__ __align__(16) __half g_W2lo[3 * TILE_W_HALVES];

// ---------------------------------------------------------------------------
// Helpers
// ---------------------------------------------------------------------------
__device__ __forceinline__ uint32_t smem_u32(const void* p) {
    uint32_t a;
    asm("{ .reg .u64 t; cvta.to.shared.u64 t, %1; cvt.u32.u64 %0, t; }"
        : "=r"(a) : "l"(p));
    return a;
}

__device__ __forceinline__ void cp16(uint32_t s, const void* g) {
    asm volatile("{\n\t.reg .u64 gp;\n\tcvta.to.global.u64 gp, %1;\n\t"
                 "cp.async.cg.shared.global [%0], [gp], 16;\n\t}"
                 :: "r"(s), "l"(g) : "memory");
}
#define CP_COMMIT() asm volatile("cp.async.commit_group;" ::: "memory")
#define CP_WAIT0()  asm volatile("cp.async.wait_group 0;" ::: "memory")

__device__ __forceinline__ void mma16816(float* c,
    uint32_t a0, uint32_t a1, uint32_t a2, uint32_t a3,
    uint32_t b0, uint32_t b1)
{
    asm volatile(
        "mma.sync.aligned.m16n8k16.row.col.f32.f16.f16.f32 "
        "{%0,%1,%2,%3}, {%4,%5,%6,%7}, {%8,%9}, {%0,%1,%2,%3};"
        : "+f"(c[0]), "+f"(c[1]), "+f"(c[2]), "+f"(c[3])
        : "r"(a0), "r"(a1), "r"(a2), "r"(a3), "r"(b0), "r"(b1));
}

__device__ __forceinline__ void split_h2(float v0, float v1,
                                         uint32_t& hi, uint32_t& lo)
{
    __half2 h = __float22half2_rn(make_float2(v0, v1));
    float r0 = v0 - __low2float(h);
    float r1 = v1 - __high2float(h);
    __half2 l = __float22half2_rn(make_float2(r0, r1));
    hi = *(uint32_t*)&h;
    lo = *(uint32_t*)&l;
}

// ---------------------------------------------------------------------------
// Precompute 1: giT = g@W1a + b1 (row-major), gjT_T = (g@W1b)^T  (fp32 exact)
// Unroll-8 K loop with 16 LDGs in flight; float4 SMEM reads.
// ---------------------------------------------------------------------------
__global__ void __launch_bounds__(256) precompute_gt(
    const float* __restrict__ g, const float* __restrict__ W1,
    const float* __restrict__ b1)
{
    __shared__ float gs[8 * DDIM];
    const int i0 = blockIdx.x * 8;
    const int tid = threadIdx.x;
    {
        const float4* src = (const float4*)(g + i0 * DDIM);
        float4* dst = (float4*)gs;
        #pragma unroll
        for (int e = 0; e < (8 * DDIM / 4) / 256; ++e)
            dst[tid + e * 256] = src[tid + e * 256];
    }
    __syncthreads();
    if (tid < HP) {
        const int h = tid;
        const bool hv = (h < HDIM);
        const int hc = hv ? h : 0;
        float acc1[8], acc2[8];
        float bb = hv ? b1[h] : 0.f;
        #pragma unroll
        for (int q = 0; q < 8; ++q) { acc1[q] = bb; acc2[q] = 0.f; }
        const float* W1a = W1 + hc;
        const float* W1b = W1 + DDIM * HDIM + hc;
        for (int d0 = 0; d0 < DDIM; d0 += 8) {
            float w1r[8], w2r[8];
            #pragma unroll
            for (int u = 0; u < 8; ++u) {
                w1r[u] = W1a[(d0 + u) * HDIM];
                w2r[u] = W1b[(d0 + u) * HDIM];
            }
            if (!hv) {
                #pragma unroll
                for (int u = 0; u < 8; ++u) { w1r[u] = 0.f; w2r[u] = 0.f; }
            }
            #pragma unroll
            for (int q = 0; q < 8; ++q) {
                const float* gq = gs + q * DDIM + d0;
                float4 ga = *(const float4*)gq;
                float4 gb = *(const float4*)(gq + 4);
                acc1[q] += ga.x * w1r[0] + ga.y * w1r[1] + ga.z * w1r[2] + ga.w * w1r[3]
                         + gb.x * w1r[4] + gb.y * w1r[5] + gb.z * w1r[6] + gb.w * w1r[7];
                acc2[q] += ga.x * w2r[0] + ga.y * w2r[1] + ga.z * w2r[2] + ga.w * w2r[3]
                         + gb.x * w2r[4] + gb.y * w2r[5] + gb.z * w2r[6] + gb.w * w2r[7];
            }
        }
        #pragma unroll
        for (int q = 0; q < 8; ++q) {
            g_giT[(i0 + q) * HP + h]   = acc1[q];
            g_gjT_T[h * NN + (i0 + q)] = acc2[q];
        }
    }
}

// ---------------------------------------------------------------------------
// Precompute 2: fp16 B-tiles [n][k] pitch 72 halves. W1c: hi only. W2: hi+lo.
// ---------------------------------------------------------------------------
__global__ void __launch_bounds__(256) precompute_wsplit(
    const float* __restrict__ W1, const float* __restrict__ W2)
{
    const int bt = blockIdx.x;
    const int tid = threadIdx.x;
    const float* W1c = W1 + 2 * DDIM * HDIM;

    if (bt < 8) {
        const int kt = bt;
        __half* dhi = g_W1hi + kt * TILE_W_HALVES;
        for (int idx = tid; idx < HP * 64; idx += 256) {
            int n = idx >> 6, k = idx & 63;
            int d = kt * 64 + k;
            float val = (n < HDIM) ? W1c[d * HDIM + n] : 0.f;
            dhi[n * 72 + k] = __float2half_rn(val);
        }
    } else {
        const int kt = bt - 8;
        __half* dhi = g_W2hi + kt * TILE_W_HALVES;
        __half* dlo = g_W2lo + kt * TILE_W_HALVES;
        for (int idx = tid; idx < HP * 64; idx += 256) {
            int n = idx >> 6, k = idx & 63;
            int kg = kt * 64 + k;
            float val = (kg < HDIM && n < HDIM) ? W2[kg * HDIM + n] : 0.f;
            __half h = __float2half_rn(val);
            __half l = __float2half_rn(val - __half2float(h));
            dhi[n * 72 + k] = h;
            dlo[n * 72 + k] = l;
        }
    }
}

// ---------------------------------------------------------------------------
// Main kernel. CTA = (i, 128 pairs). grid (2, 1024). 8 warps: wm=wid&3 (M 32),
// wn=wid>>2 (N 80). Warp tile 32x80 = 2 m16-tiles x 10 n8-tiles.
// ---------------------------------------------------------------------------
__global__ void __launch_bounds__(NTHR, 2) pair_mma_kernel(
    const float* __restrict__ g,  const float* __restrict__ sm,
    const float* __restrict__ b2, const float* __restrict__ W3,
    const float* __restrict__ b3, float* __restrict__ out)
{
    extern __shared__ char smem[];
    const uint32_t sb = smem_u32(smem);
    const int tid = threadIdx.x;
    const int wid = tid >> 5, lid = tid & 31;
    const int wm = wid & 3, wn = wid >> 2;
    const int gq = lid >> 2, t = lid & 3;     // quad row / quad lane
    const int i  = blockIdx.y;
    const int k0 = blockIdx.x * 128;

    int jrow[2][2];
    #pragma unroll
    for (int mi = 0; mi < 2; ++mi)
        #pragma unroll
        for (int h8 = 0; h8 < 2; ++h8) {
            int p = wm * 32 + mi * 16 + gq + h8 * 8;
            int j = i - WWIN + k0 + p;
            jrow[mi][h8] = min(max(j, 0), NN - 1);
        }

    // ---- accumulators, init with bias terms giT[i][col] + gjT[col][j] ----
    float acc[2][10][4];
    {
        const float* giR = g_giT + i * HP;
        #pragma unroll
        for (int nt = 0; nt < 10; ++nt)
            #pragma unroll
            for (int par = 0; par < 2; ++par) {
                int col = wn * 80 + nt * 8 + 2 * t + par;
                float gic = giR[col];
                const float* gjc = g_gjT_T + col * NN;
                #pragma unroll
                for (int mi = 0; mi < 2; ++mi)
                    #pragma unroll
                    for (int h8 = 0; h8 < 2; ++h8)
                        acc[mi][nt][h8 * 2 + par] = gic + gjc[jrow[mi][h8]];
            }
    }

    const uint32_t a_off = (uint32_t)(((wm * 32 + gq) * 36 + t) * 4);
    const uint32_t b_off = (uint32_t)(((wn * 80 + gq) * 36 + t) * 4);

    // =================== Stage 1: acc += (gi*gj) @ W1c ====================
    const int pA = tid >> 1;          // A-prep row 0..127
    const int sA = tid & 1;           // which 32-col half
    const int jA = min(max(i - WWIN + k0 + pA, 0), NN - 1);
    const float4* giRow4 = (const float4*)(g + i * DDIM);
    const float4* gjRow4 = (const float4*)(g + jA * DDIM);

    for (int kt = 0; kt < 8; ++kt) {
        // --- B-hi tile via cp.async (issued first, overlapped with A-prep) ---
        {
            const char* shi = (const char*)(g_W1hi + kt * TILE_W_HALVES);
            for (int x = tid; x < TILE_W_U4; x += NTHR)
                cp16(sb + BHI + x * 16, shi + x * 16);
            CP_COMMIT();
        }
        // --- A prep: products -> split fp16 hi/lo ---
        {
            const int qb = kt * 16 + sA * 8;
            char* dsthi = smem + A1HI + pA * 144 + sA * 64;
            char* dstlo = smem + A1LO + pA * 144 + sA * 64;
            #pragma unroll
            for (int q = 0; q < 8; ++q) {
                float4 a = giRow4[qb + q];
                float4 b = gjRow4[qb + q];
                float v0 = a.x * b.x, v1 = a.y * b.y, v2 = a.z * b.z, v3 = a.w * b.w;
                uint32_t h0, l0, h1, l1;
                split_h2(v0, v1, h0, l0);
                split_h2(v2, v3, h1, l1);
                *(uint2*)(dsthi + q * 8) = make_uint2(h0, h1);
                *(uint2*)(dstlo + q * 8) = make_uint2(l0, l1);
            }
        }
        CP_WAIT0();
        __syncthreads();

        #pragma unroll
        for (int ks = 0; ks < 4; ++ks) {
            const uint32_t ko = ks * 32;
            uint32_t ah[2][4], al[2][4];
            #pragma unroll
            for (int mi = 0; mi < 2; ++mi) {
                uint32_t base = a_off + mi * 2304 + ko;
                ah[mi][0] = *(const uint32_t*)(smem + A1HI + base);
                ah[mi][1] = *(const uint32_t*)(smem + A1HI + base + 1152);
                ah[mi][2] = *(const uint32_t*)(smem + A1HI + base + 16);
                ah[mi][3] = *(const uint32_t*)(smem + A1HI + base + 1168);
                al[mi][0] = *(const uint32_t*)(smem + A1LO + base);
                al[mi][1] = *(const uint32_t*)(smem + A1LO + base + 1152);
                al[mi][2] = *(const uint32_t*)(smem + A1LO + base + 16);
                al[mi][3] = *(const uint32_t*)(smem + A1LO + base + 1168);
            }
            #pragma unroll
            for (int nt = 0; nt < 10; ++nt) {
                uint32_t bb = b_off + nt * 1152 + ko;
                uint32_t bh0 = *(const uint32_t*)(smem + BHI + bb);
                uint32_t bh1 = *(const uint32_t*)(smem + BHI + bb + 16);
                #pragma unroll
                for (int mi = 0; mi < 2; ++mi) {
                    mma16816(acc[mi][nt], ah[mi][0], ah[mi][1], ah[mi][2], ah[mi][3], bh0, bh1);
                    mma16816(acc[mi][nt], al[mi][0], al[mi][1], al[mi][2], al[mi][3], bh0, bh1);
                }
            }
        }
        __syncthreads();
    }

    // ============ h1 = relu(acc) -> SMEM (single fp16, 3 k-tiles) ==========
    {
        #pragma unroll
        for (int mi = 0; mi < 2; ++mi)
            #pragma unroll
            for (int h8 = 0; h8 < 2; ++h8) {
                int row = wm * 32 + mi * 16 + gq + h8 * 8;
                #pragma unroll
                for (int nt = 0; nt < 10; ++nt) {
                    int col = wn * 80 + nt * 8 + 2 * t;
                    float v0 = fmaxf(acc[mi][nt][h8 * 2 + 0], 0.f);
                    float v1 = fmaxf(acc[mi][nt][h8 * 2 + 1], 0.f);
                    __half2 h = __float22half2_rn(make_float2(v0, v1));
                    int tile = col >> 6;
                    uint32_t off = (uint32_t)(tile * 18432 + row * 144 + (col & 63) * 2);
                    *(uint32_t*)(smem + off) = *(uint32_t*)&h;
                }
            }
        // zero-fill tile2 cols 160..191
        for (int idx = tid; idx < 128 * 16; idx += NTHR) {
            int row = idx >> 4, w = idx & 15;
            *(uint32_t*)(smem + 36864 + row * 144 + 64 + w * 4) = 0u;
        }
    }

    // ---- re-init acc with b2 for stage 2 ----
    #pragma unroll
    for (int nt = 0; nt < 10; ++nt)
        #pragma unroll
        for (int par = 0; par < 2; ++par) {
            int col = wn * 80 + nt * 8 + 2 * t + par;
            float bv = (col < HDIM) ? b2[col] : 0.f;
            #pragma unroll
            for (int mi = 0; mi < 2; ++mi)
                #pragma unroll
                for (int h8 = 0; h8 < 2; ++h8)
                    acc[mi][nt][h8 * 2 + par] = bv;
        }

    // =================== Stage 2: acc += relu(h1) @ W2 =====================
    for (int kt2 = 0; kt2 < 3; ++kt2) {
        {
            const char* shi = (const char*)(g_W2hi + kt2 * TILE_W_HALVES);
            const char* slo = (const char*)(g_W2lo + kt2 * TILE_W_HALVES);
            for (int x = tid; x < TILE_W_U4; x += NTHR) {
                cp16(sb + B2HI + x * 16, shi + x * 16);
                cp16(sb + B2LO + x * 16, slo + x * 16);
            }
            CP_COMMIT();
            CP_WAIT0();
        }
        __syncthreads();
        const uint32_t tbase = (uint32_t)(kt2 * 18432);
        #pragma unroll
        for (int ks = 0; ks < 4; ++ks) {
            const uint32_t ko = ks * 32;
            uint32_t af[2][4];
            #pragma unroll
            for (int mi = 0; mi < 2; ++mi) {
                uint32_t base = tbase + a_off + mi * 2304 + ko;
                af[mi][0] = *(const uint32_t*)(smem + base);
                af[mi][1] = *(const uint32_t*)(smem + base + 1152);
                af[mi][2] = *(const uint32_t*)(smem + base + 16);
                af[mi][3] = *(const uint32_t*)(smem + base + 1168);
            }
            #pragma unroll
            for (int nt = 0; nt < 10; ++nt) {
                uint32_t bb = b_off + nt * 1152 + ko;
                uint32_t bh0 = *(const uint32_t*)(smem + B2HI + bb);
                uint32_t bh1 = *(const uint32_t*)(smem + B2HI + bb + 16);
                uint32_t bl0 = *(const uint32_t*)(smem + B2LO + bb);
                uint32_t bl1 = *(const uint32_t*)(smem + B2LO + bb + 16);
                #pragma unroll
                for (int mi = 0; mi < 2; ++mi) {
                    mma16816(acc[mi][nt], af[mi][0], af[mi][1], af[mi][2], af[mi][3], bh0, bh1);
                    mma16816(acc[mi][nt], af[mi][0], af[mi][1], af[mi][2], af[mi][3], bl0, bl1);
                }
            }
        }
        __syncthreads();
    }

    // =================== Epilogue: relu(acc) @ W3, reduce ==================
    float rsum[2][2] = {{0.f, 0.f}, {0.f, 0.f}};
    #pragma unroll
    for (int nt = 0; nt < 10; ++nt)
        #pragma unroll
        for (int par = 0; par < 2; ++par) {
            int col = wn * 80 + nt * 8 + 2 * t + par;
            float w3 = (col < HDIM) ? W3[col] : 0.f;
            #pragma unroll
            for (int mi = 0; mi < 2; ++mi)
                #pragma unroll
                for (int h8 = 0; h8 < 2; ++h8)
                    rsum[mi][h8] += fmaxf(acc[mi][nt][h8 * 2 + par], 0.f) * w3;
        }
    #pragma unroll
    for (int mi = 0; mi < 2; ++mi)
        #pragma unroll
        for (int h8 = 0; h8 < 2; ++h8) {
            float v = rsum[mi][h8];
            v += __shfl_xor_sync(0xffffffffu, v, 1);
            v += __shfl_xor_sync(0xffffffffu, v, 2);
            rsum[mi][h8] = v;
        }

    float* sred = (float*)(smem + SRED);
    if (wn == 0 && t == 0) {
        #pragma unroll
        for (int mi = 0; mi < 2; ++mi)
            #pragma unroll
            for (int h8 = 0; h8 < 2; ++h8)
                sred[wm * 32 + mi * 16 + gq + h8 * 8] = rsum[mi][h8];
    }
    __syncthreads();
    if (wn == 1 && t == 0) {
        float smi = sm[i];
        float bb3 = b3[0];
        #pragma unroll
        for (int mi = 0; mi < 2; ++mi)
            #pragma unroll
            for (int h8 = 0; h8 < 2; ++h8) {
                int p = wm * 32 + mi * 16 + gq + h8 * 8;
                int k = k0 + p;
                int j = i - WWIN + k;
                float tot = rsum[mi][h8] + sred[p];
                if (k < WWIN) {
                    float val = 0.f;
                    if (j >= 0) val = tot + bb3 + smi + sm[j];
                    out[i * OUTW + k] = val;
                } else if (k == WWIN) {
                    out[i * OUTW + k] = 0.f;   // epsilon column
                }
            }
    }
}

// ---------------------------------------------------------------------------
extern "C" void kernel_launch(void* const* d_in, const int* in_sizes, int n_in,
                              void* d_out, int out_size)
{
    const float* g  = (const float*)d_in[0];
    const float* sm = (const float*)d_in[1];
    const float* W1 = (const float*)d_in[2];
    const float* b1 = (const float*)d_in[3];
    const float* W2 = (const float*)d_in[4];
    const float* b2 = (const float*)d_in[5];
    const float* W3 = (const float*)d_in[6];
    const float* b3 = (const float*)d_in[7];
    float* out = (float*)d_out;

    cudaFuncSetAttribute(pair_mma_kernel,
                         cudaFuncAttributeMaxDynamicSharedMemorySize, SMEM_TOTAL);

    precompute_gt<<<NN / 8, 256>>>(g, W1, b1);
    precompute_wsplit<<<11, 256>>>(W1, W2);

    dim3 grid(2, NN);
    pair_mma_kernel<<<grid, NTHR, SMEM_TOTAL>>>(g, sm, b2, W3, b3, out);
}

// round 5
// speedup vs baseline: 3.8762x; 1.2631x over previous
#include <cuda_runtime.h>
#include <cuda_fp16.h>
#include <cstdint>

#define NN    1024
#define DDIM  512
#define HDIM  150
#define HP    160
#define WWIN  250
#define OUTW  251
#define NTHR  256

// ---- dynamic SMEM byte offsets ----
// stage1: A0=0(18432) A1=18432(18432) | Bphys0=36864(23040) Bphys1=59904(23040)
// stage2: h1 tiles at 0 / 18432 / 36864 ; B2HI=59904, B2LO=82944
#define SA0   0
#define SA1   18432
#define SB0   36864
#define SB1   59904
#define B2HI  59904
#define B2LO  82944
#define SRED  105984
#define SMEM_TOTAL 106496

#define TILE_W_HALVES 11520     // 160*72
#define TILE_W_BYTES  23040
#define TILE_W_U4     1440

// ---------------------------------------------------------------------------
// Device scratch
// ---------------------------------------------------------------------------
__device__ float g_giT[NN * HP];      // g@W1a + b1, [i][h], zero pad h>=150
__device__ float g_gjT_T[HP * NN];    // (g@W1b)^T, [h][i], zero pad
__device__ __align__(16) __half g_W1hi[8 * TILE_W_HALVES];
__device__ __align__(16) __half g_W2hi[3 * TILE_W_HALVES];
__device__ __align__(16) __half g_W2lo[3 * TILE_W_HALVES];

// ---------------------------------------------------------------------------
// Helpers
// ---------------------------------------------------------------------------
__device__ __forceinline__ uint32_t smem_u32(const void* p) {
    uint32_t a;
    asm("{ .reg .u64 t; cvta.to.shared.u64 t, %1; cvt.u32.u64 %0, t; }"
        : "=r"(a) : "l"(p));
    return a;
}

__device__ __forceinline__ void cp16(uint32_t s, const void* g) {
    asm volatile("{\n\t.reg .u64 gp;\n\tcvta.to.global.u64 gp, %1;\n\t"
                 "cp.async.cg.shared.global [%0], [gp], 16;\n\t}"
                 :: "r"(s), "l"(g) : "memory");
}
#define CP_COMMIT() asm volatile("cp.async.commit_group;" ::: "memory")
#define CP_WAIT0()  asm volatile("cp.async.wait_group 0;" ::: "memory")

__device__ __forceinline__ void ldsm4(uint32_t* r, uint32_t addr) {
    asm volatile("ldmatrix.sync.aligned.m8n8.x4.shared.b16 {%0,%1,%2,%3}, [%4];"
        : "=r"(r[0]), "=r"(r[1]), "=r"(r[2]), "=r"(r[3]) : "r"(addr));
}

__device__ __forceinline__ void mma16816(float* c,
    uint32_t a0, uint32_t a1, uint32_t a2, uint32_t a3,
    uint32_t b0, uint32_t b1)
{
    asm volatile(
        "mma.sync.aligned.m16n8k16.row.col.f32.f16.f16.f32 "
        "{%0,%1,%2,%3}, {%4,%5,%6,%7}, {%8,%9}, {%0,%1,%2,%3};"
        : "+f"(c[0]), "+f"(c[1]), "+f"(c[2]), "+f"(c[3])
        : "r"(a0), "r"(a1), "r"(a2), "r"(a3), "r"(b0), "r"(b1));
}

// ---------------------------------------------------------------------------
// Precompute 1: giT = g@W1a + b1 (row-major), gjT_T = (g@W1b)^T  (fp32 exact)
// 640 threads: h = tid%160, ks = tid/160 (4-way K-split) + SMEM reduce.
// ---------------------------------------------------------------------------
__global__ void __launch_bounds__(640) precompute_gt(
    const float* __restrict__ g, const float* __restrict__ W1,
    const float* __restrict__ b1)
{
    __shared__ float gs[8 * DDIM];              // 16 KB
    __shared__ float red[3 * 160 * 16];         // 30 KB
    const int i0 = blockIdx.x * 8;
    const int tid = threadIdx.x;
    {
        const float4* src = (const float4*)(g + i0 * DDIM);
        float4* dst = (float4*)gs;
        for (int x = tid; x < (8 * DDIM) / 4; x += 640) dst[x] = src[x];
    }
    __syncthreads();

    const int h  = tid % 160;
    const int ks = tid / 160;
    const bool hv = (h < HDIM);
    const int hc = hv ? h : 0;
    float acc1[8], acc2[8];
    float bb = (hv && ks == 0) ? b1[h] : 0.f;
    #pragma unroll
    for (int q = 0; q < 8; ++q) { acc1[q] = bb; acc2[q] = 0.f; }
    const float* W1a = W1 + hc;
    const float* W1b = W1 + DDIM * HDIM + hc;
    const int d0b = ks * 128;
    for (int d0 = d0b; d0 < d0b + 128; d0 += 8) {
        float w1r[8], w2r[8];
        #pragma unroll
        for (int u = 0; u < 8; ++u) {
            w1r[u] = W1a[(d0 + u) * HDIM];
            w2r[u] = W1b[(d0 + u) * HDIM];
        }
        if (!hv) {
            #pragma unroll
            for (int u = 0; u < 8; ++u) { w1r[u] = 0.f; w2r[u] = 0.f; }
        }
        #pragma unroll
        for (int q = 0; q < 8; ++q) {
            const float* gq = gs + q * DDIM + d0;
            float4 ga = *(const float4*)gq;
            float4 gb = *(const float4*)(gq + 4);
            acc1[q] += ga.x * w1r[0] + ga.y * w1r[1] + ga.z * w1r[2] + ga.w * w1r[3]
                     + gb.x * w1r[4] + gb.y * w1r[5] + gb.z * w1r[6] + gb.w * w1r[7];
            acc2[q] += ga.x * w2r[0] + ga.y * w2r[1] + ga.z * w2r[2] + ga.w * w2r[3]
                     + gb.x * w2r[4] + gb.y * w2r[5] + gb.z * w2r[6] + gb.w * w2r[7];
        }
    }
    if (ks > 0) {
        float* r = red + ((ks - 1) * 160 + h) * 16;
        #pragma unroll
        for (int q = 0; q < 8; ++q) { r[q] = acc1[q]; r[8 + q] = acc2[q]; }
    }
    __syncthreads();
    if (ks == 0) {
        #pragma unroll
        for (int s = 0; s < 3; ++s) {
            const float* r = red + (s * 160 + h) * 16;
            #pragma unroll
            for (int q = 0; q < 8; ++q) { acc1[q] += r[q]; acc2[q] += r[8 + q]; }
        }
        #pragma unroll
        for (int q = 0; q < 8; ++q) {
            g_giT[(i0 + q) * HP + h]   = acc1[q];
            g_gjT_T[h * NN + (i0 + q)] = acc2[q];
        }
    }
}

// ---------------------------------------------------------------------------
// Precompute 2: fp16 B-tiles [n][k] pitch 72 halves. W1c: hi only. W2: hi+lo.
// ---------------------------------------------------------------------------
__global__ void __launch_bounds__(256) precompute_wsplit(
    const float* __restrict__ W1, const float* __restrict__ W2)
{
    const int bt = blockIdx.x;
    const int tid = threadIdx.x;
    const float* W1c = W1 + 2 * DDIM * HDIM;

    if (bt < 8) {
        const int kt = bt;
        __half* dhi = g_W1hi + kt * TILE_W_HALVES;
        for (int idx = tid; idx < HP * 64; idx += 256) {
            int n = idx >> 6, k = idx & 63;
            int d = kt * 64 + k;
            float val = (n < HDIM) ? W1c[d * HDIM + n] : 0.f;
            dhi[n * 72 + k] = __float2half_rn(val);
        }
    } else {
        const int kt = bt - 8;
        __half* dhi = g_W2hi + kt * TILE_W_HALVES;
        __half* dlo = g_W2lo + kt * TILE_W_HALVES;
        for (int idx = tid; idx < HP * 64; idx += 256) {
            int n = idx >> 6, k = idx & 63;
            int kg = kt * 64 + k;
            float val = (kg < HDIM && n < HDIM) ? W2[kg * HDIM + n] : 0.f;
            __half h = __float2half_rn(val);
            __half l = __float2half_rn(val - __half2float(h));
            dhi[n * 72 + k] = h;
            dlo[n * 72 + k] = l;
        }
    }
}

// ---------------------------------------------------------------------------
// Main kernel. CTA = (i, 128 pairs). grid (2, 1024). 8 warps: wm=wid&3 (M 32),
// wn=wid>>2 (N 80). Warp tile 32x80. Stage1: pure fp16, double-buffered.
// ---------------------------------------------------------------------------
__global__ void __launch_bounds__(NTHR, 2) pair_mma_kernel(
    const float* __restrict__ g,  const float* __restrict__ sm,
    const float* __restrict__ b2, const float* __restrict__ W3,
    const float* __restrict__ b3, float* __restrict__ out)
{
    extern __shared__ char smem[];
    const uint32_t sb = smem_u32(smem);
    const int tid = threadIdx.x;
    const int wid = tid >> 5, lid = tid & 31;
    const int wm = wid & 3, wn = wid >> 2;
    const int gq = lid >> 2, t = lid & 3;
    const int i  = blockIdx.y;
    const int k0 = blockIdx.x * 128;

    int jrow[2][2];
    #pragma unroll
    for (int mi = 0; mi < 2; ++mi)
        #pragma unroll
        for (int h8 = 0; h8 < 2; ++h8) {
            int p = wm * 32 + mi * 16 + gq + h8 * 8;
            int j = i - WWIN + k0 + p;
            jrow[mi][h8] = min(max(j, 0), NN - 1);
        }

    // ---- accumulators, init with bias terms giT[i][col] + gjT[col][j] ----
    float acc[2][10][4];
    {
        const float* giR = g_giT + i * HP;
        #pragma unroll
        for (int nt = 0; nt < 10; ++nt)
            #pragma unroll
            for (int par = 0; par < 2; ++par) {
                int col = wn * 80 + nt * 8 + 2 * t + par;
                float gic = giR[col];
                const float* gjc = g_gjT_T + col * NN;
                #pragma unroll
                for (int mi = 0; mi < 2; ++mi)
                    #pragma unroll
                    for (int h8 = 0; h8 < 2; ++h8)
                        acc[mi][nt][h8 * 2 + par] = gic + gjc[jrow[mi][h8]];
            }
    }

    // ---- ldmatrix lane offsets ----
    const int mq = lid >> 3, rr = lid & 7;
    uint32_t aOff[2], bOff[5];
    #pragma unroll
    for (int mi = 0; mi < 2; ++mi)
        aOff[mi] = (uint32_t)((wm * 32 + mi * 16 + (mq & 1) * 8 + rr) * 144 + (mq >> 1) * 16);
    #pragma unroll
    for (int ntp = 0; ntp < 5; ++ntp)
        bOff[ntp] = (uint32_t)((wn * 80 + (ntp * 2 + (mq >> 1)) * 8 + rr) * 144 + (mq & 1) * 16);

    // ---- A-prep identity ----
    const int pA = tid >> 1;
    const int sA = tid & 1;
    const int jA = min(max(i - WWIN + k0 + pA, 0), NN - 1);
    const float4* giRow4 = (const float4*)(g + i * DDIM);
    const float4* gjRow4 = (const float4*)(g + jA * DDIM);

    // =================== Stage 1: acc += (gi*gj) @ W1c (fp16) ==============
    // prologue
    {
        const char* src = (const char*)g_W1hi;            // kt=0 tile -> SB1
        for (int x = tid; x < TILE_W_U4; x += NTHR)
            cp16(sb + SB1 + x * 16, src + x * 16);
        CP_COMMIT();
        const int qb = sA * 8;
        char* dst = smem + SA0 + pA * 144 + sA * 64;
        #pragma unroll
        for (int q = 0; q < 8; ++q) {
            float4 a = giRow4[qb + q];
            float4 b = gjRow4[qb + q];
            __half2 h0 = __float22half2_rn(make_float2(a.x * b.x, a.y * b.y));
            __half2 h1 = __float22half2_rn(make_float2(a.z * b.z, a.w * b.w));
            *(uint2*)(dst + q * 8) = make_uint2(*(uint32_t*)&h0, *(uint32_t*)&h1);
        }
        CP_WAIT0();
        __syncthreads();
    }

    for (int kt = 0; kt < 8; ++kt) {
        // cp next B (or prefetch stage2's first W2 tiles on the last iter)
        if (kt < 7) {
            const char* src = (const char*)(g_W1hi + (kt + 1) * TILE_W_HALVES);
            uint32_t dstB = sb + (((kt + 1) & 1) ? SB0 : SB1);
            for (int x = tid; x < TILE_W_U4; x += NTHR)
                cp16(dstB + x * 16, src + x * 16);
        } else {
            const char* shi = (const char*)g_W2hi;
            const char* slo = (const char*)g_W2lo;
            for (int x = tid; x < TILE_W_U4; x += NTHR) {
                cp16(sb + B2HI + x * 16, shi + x * 16);
                cp16(sb + B2LO + x * 16, slo + x * 16);
            }
        }
        CP_COMMIT();

        // MMA(kt)
        const uint32_t aB = sb + ((kt & 1) ? SA1 : SA0);
        const uint32_t bB = sb + ((kt & 1) ? SB0 : SB1);
        #pragma unroll
        for (int ks = 0; ks < 4; ++ks) {
            uint32_t ah0[4], ah1[4];
            ldsm4(ah0, aB + aOff[0] + ks * 32);
            ldsm4(ah1, aB + aOff[1] + ks * 32);
            #pragma unroll
            for (int ntp = 0; ntp < 5; ++ntp) {
                uint32_t bf[4];
                ldsm4(bf, bB + bOff[ntp] + ks * 32);
                mma16816(acc[0][2 * ntp],     ah0[0], ah0[1], ah0[2], ah0[3], bf[0], bf[1]);
                mma16816(acc[1][2 * ntp],     ah1[0], ah1[1], ah1[2], ah1[3], bf[0], bf[1]);
                mma16816(acc[0][2 * ntp + 1], ah0[0], ah0[1], ah0[2], ah0[3], bf[2], bf[3]);
                mma16816(acc[1][2 * ntp + 1], ah1[0], ah1[1], ah1[2], ah1[3], bf[2], bf[3]);
            }
        }

        // prep next A
        if (kt < 7) {
            const int qb = (kt + 1) * 16 + sA * 8;
            char* dst = smem + (((kt + 1) & 1) ? SA1 : SA0) + pA * 144 + sA * 64;
            #pragma unroll
            for (int q = 0; q < 8; ++q) {
                float4 a = giRow4[qb + q];
                float4 b = gjRow4[qb + q];
                __half2 h0 = __float22half2_rn(make_float2(a.x * b.x, a.y * b.y));
                __half2 h1 = __float22half2_rn(make_float2(a.z * b.z, a.w * b.w));
                *(uint2*)(dst + q * 8) = make_uint2(*(uint32_t*)&h0, *(uint32_t*)&h1);
            }
        }
        CP_WAIT0();
        __syncthreads();
    }

    // ============ h1 = relu(acc) -> SMEM (single fp16, 3 k-tiles) ==========
    {
        #pragma unroll
        for (int mi = 0; mi < 2; ++mi)
            #pragma unroll
            for (int h8 = 0; h8 < 2; ++h8) {
                int row = wm * 32 + mi * 16 + gq + h8 * 8;
                #pragma unroll
                for (int nt = 0; nt < 10; ++nt) {
                    int col = wn * 80 + nt * 8 + 2 * t;
                    float v0 = fmaxf(acc[mi][nt][h8 * 2 + 0], 0.f);
                    float v1 = fmaxf(acc[mi][nt][h8 * 2 + 1], 0.f);
                    __half2 h = __float22half2_rn(make_float2(v0, v1));
                    int tile = col >> 6;
                    uint32_t off = (uint32_t)(tile * 18432 + row * 144 + (col & 63) * 2);
                    *(uint32_t*)(smem + off) = *(uint32_t*)&h;
                }
            }
        for (int idx = tid; idx < 128 * 16; idx += NTHR) {
            int row = idx >> 4, w = idx & 15;
            *(uint32_t*)(smem + 36864 + row * 144 + 64 + w * 4) = 0u;
        }
    }

    // ---- re-init acc with b2 for stage 2 ----
    #pragma unroll
    for (int nt = 0; nt < 10; ++nt)
        #pragma unroll
        for (int par = 0; par < 2; ++par) {
            int col = wn * 80 + nt * 8 + 2 * t + par;
            float bv = (col < HDIM) ? b2[col] : 0.f;
            #pragma unroll
            for (int mi = 0; mi < 2; ++mi)
                #pragma unroll
                for (int h8 = 0; h8 < 2; ++h8)
                    acc[mi][nt][h8 * 2 + par] = bv;
        }
    __syncthreads();

    // =================== Stage 2: acc += relu(h1) @ W2 (split W2) ==========
    for (int kt2 = 0; kt2 < 3; ++kt2) {
        const uint32_t aB2 = sb + kt2 * 18432;
        #pragma unroll
        for (int ks = 0; ks < 4; ++ks) {
            uint32_t af0[4], af1[4];
            ldsm4(af0, aB2 + aOff[0] + ks * 32);
            ldsm4(af1, aB2 + aOff[1] + ks * 32);
            #pragma unroll
            for (int ntp = 0; ntp < 5; ++ntp) {
                uint32_t bh[4], bl[4];
                ldsm4(bh, sb + B2HI + bOff[ntp] + ks * 32);
                mma16816(acc[0][2 * ntp],     af0[0], af0[1], af0[2], af0[3], bh[0], bh[1]);
                mma16816(acc[1][2 * ntp],     af1[0], af1[1], af1[2], af1[3], bh[0], bh[1]);
                mma16816(acc[0][2 * ntp + 1], af0[0], af0[1], af0[2], af0[3], bh[2], bh[3]);
                mma16816(acc[1][2 * ntp + 1], af1[0], af1[1], af1[2], af1[3], bh[2], bh[3]);
                ldsm4(bl, sb + B2LO + bOff[ntp] + ks * 32);
                mma16816(acc[0][2 * ntp],     af0[0], af0[1], af0[2], af0[3], bl[0], bl[1]);
                mma16816(acc[1][2 * ntp],     af1[0], af1[1], af1[2], af1[3], bl[0], bl[1]);
                mma16816(acc[0][2 * ntp + 1], af0[0], af0[1], af0[2], af0[3], bl[2], bl[3]);
                mma16816(acc[1][2 * ntp + 1], af1[0], af1[1], af1[2], af1[3], bl[2], bl[3]);
            }
        }
        __syncthreads();
        if (kt2 < 2) {
            const char* shi = (const char*)(g_W2hi + (kt2 + 1) * TILE_W_HALVES);
            const char* slo = (const char*)(g_W2lo + (kt2 + 1) * TILE_W_HALVES);
            for (int x = tid; x < TILE_W_U4; x += NTHR) {
                cp16(sb + B2HI + x * 16, shi + x * 16);
                cp16(sb + B2LO + x * 16, slo + x * 16);
            }
            CP_COMMIT();
            CP_WAIT0();
            __syncthreads();
        }
    }

    // =================== Epilogue: relu(acc) @ W3, reduce ==================
    float rsum[2][2] = {{0.f, 0.f}, {0.f, 0.f}};
    #pragma unroll
    for (int nt = 0; nt < 10; ++nt)
        #pragma unroll
        for (int par = 0; par < 2; ++par) {
            int col = wn * 80 + nt * 8 + 2 * t + par;
            float w3 = (col < HDIM) ? W3[col] : 0.f;
            #pragma unroll
            for (int mi = 0; mi < 2; ++mi)
                #pragma unroll
                for (int h8 = 0; h8 < 2; ++h8)
                    rsum[mi][h8] += fmaxf(acc[mi][nt][h8 * 2 + par], 0.f) * w3;
        }
    #pragma unroll
    for (int mi = 0; mi < 2; ++mi)
        #pragma unroll
        for (int h8 = 0; h8 < 2; ++h8) {
            float v = rsum[mi][h8];
            v += __shfl_xor_sync(0xffffffffu, v, 1);
            v += __shfl_xor_sync(0xffffffffu, v, 2);
            rsum[mi][h8] = v;
        }

    float* sred = (float*)(smem + SRED);
    if (wn == 0 && t == 0) {
        #pragma unroll
        for (int mi = 0; mi < 2; ++mi)
            #pragma unroll
            for (int h8 = 0; h8 < 2; ++h8)
                sred[wm * 32 + mi * 16 + gq + h8 * 8] = rsum[mi][h8];
    }
    __syncthreads();
    if (wn == 1 && t == 0) {
        float smi = sm[i];
        float bb3 = b3[0];
        #pragma unroll
        for (int mi = 0; mi < 2; ++mi)
            #pragma unroll
            for (int h8 = 0; h8 < 2; ++h8) {
                int p = wm * 32 + mi * 16 + gq + h8 * 8;
                int k = k0 + p;
                int j = i - WWIN + k;
                float tot = rsum[mi][h8] + sred[p];
                if (k < WWIN) {
                    float val = 0.f;
                    if (j >= 0) val = tot + bb3 + smi + sm[j];
                    out[i * OUTW + k] = val;
                } else if (k == WWIN) {
                    out[i * OUTW + k] = 0.f;   // epsilon column
                }
            }
    }
}

// ---------------------------------------------------------------------------
extern "C" void kernel_launch(void* const* d_in, const int* in_sizes, int n_in,
                              void* d_out, int out_size)
{
    const float* g  = (const float*)d_in[0];
    const float* sm = (const float*)d_in[1];
    const float* W1 = (const float*)d_in[2];
    const float* b1 = (const float*)d_in[3];
    const float* W2 = (const float*)d_in[4];
    const float* b2 = (const float*)d_in[5];
    const float* W3 = (const float*)d_in[6];
    const float* b3 = (const float*)d_in[7];
    float* out = (float*)d_out;

    cudaFuncSetAttribute(pair_mma_kernel,
                         cudaFuncAttributeMaxDynamicSharedMemorySize, SMEM_TOTAL);

    precompute_gt<<<NN / 8, 640>>>(g, W1, b1);
    precompute_wsplit<<<11, 256>>>(W1, W2);

    dim3 grid(2, NN);
    pair_mma_kernel<<<grid, NTHR, SMEM_TOTAL>>>(g, sm, b2, W3, b3, out);
}

// round 6
// speedup vs baseline: 4.3517x; 1.1227x over previous
#include <cuda_runtime.h>
#include <cuda_fp16.h>
#include <cstdint>

#define NN    1024
#define DDIM  512
#define HDIM  150
#define HP    160
#define WWIN  250
#define OUTW  251
#define NTHR  256

// ---- dynamic SMEM byte offsets ----
// stage1: A0=0(18432) A1=18432(18432) | B0=36864(23040) B1=59904(23040)
// stage2: h1 tiles at 0 / 18432 / 36864 ; B2 double buffer at 59904 / 82944
#define SA0   0
#define SA1   18432
#define SB0   36864
#define SB1   59904
#define B2B0  59904
#define B2B1  82944
#define SRED  105984
#define SMEM_TOTAL 106496

#define TILE_W_HALVES 11520     // 160*72
#define TILE_W_U4     1440

// ---------------------------------------------------------------------------
// Device scratch
// ---------------------------------------------------------------------------
__device__ float g_giT[NN * HP];      // g@W1a + b1, [i][h], zero pad h>=150
__device__ float g_gjT_T[HP * NN];    // (g@W1b)^T, [h][i], zero pad
__device__ __align__(16) __half g_W1hi[8 * TILE_W_HALVES];
__device__ __align__(16) __half g_W2hi[3 * TILE_W_HALVES];

// ---------------------------------------------------------------------------
// Helpers
// ---------------------------------------------------------------------------
__device__ __forceinline__ uint32_t smem_u32(const void* p) {
    uint32_t a;
    asm("{ .reg .u64 t; cvta.to.shared.u64 t, %1; cvt.u32.u64 %0, t; }"
        : "=r"(a) : "l"(p));
    return a;
}

__device__ __forceinline__ void cp16(uint32_t s, const void* g) {
    asm volatile("{\n\t.reg .u64 gp;\n\tcvta.to.global.u64 gp, %1;\n\t"
                 "cp.async.cg.shared.global [%0], [gp], 16;\n\t}"
                 :: "r"(s), "l"(g) : "memory");
}
#define CP_COMMIT() asm volatile("cp.async.commit_group;" ::: "memory")
#define CP_WAIT0()  asm volatile("cp.async.wait_group 0;" ::: "memory")

__device__ __forceinline__ void ldsm4(uint32_t* r, uint32_t addr) {
    asm volatile("ldmatrix.sync.aligned.m8n8.x4.shared.b16 {%0,%1,%2,%3}, [%4];"
        : "=r"(r[0]), "=r"(r[1]), "=r"(r[2]), "=r"(r[3]) : "r"(addr));
}

__device__ __forceinline__ void mma16816(float* c,
    uint32_t a0, uint32_t a1, uint32_t a2, uint32_t a3,
    uint32_t b0, uint32_t b1)
{
    asm volatile(
        "mma.sync.aligned.m16n8k16.row.col.f32.f16.f16.f32 "
        "{%0,%1,%2,%3}, {%4,%5,%6,%7}, {%8,%9}, {%0,%1,%2,%3};"
        : "+f"(c[0]), "+f"(c[1]), "+f"(c[2]), "+f"(c[3])
        : "r"(a0), "r"(a1), "r"(a2), "r"(a3), "r"(b0), "r"(b1));
}

// ---------------------------------------------------------------------------
// Precompute 1: giT = g@W1a + b1 (row-major), gjT_T = (g@W1b)^T  (fp32 exact)
// 256 blocks x 640 thr: 4 rows/block, h = tid%160, ks = tid/160 (4-way K-split).
// ---------------------------------------------------------------------------
__global__ void __launch_bounds__(640) precompute_gt(
    const float* __restrict__ g, const float* __restrict__ W1,
    const float* __restrict__ b1)
{
    __shared__ float gs[4 * DDIM];
    __shared__ float red[3 * 160 * 8];
    const int i0 = blockIdx.x * 4;
    const int tid = threadIdx.x;
    {
        const float4* src = (const float4*)(g + i0 * DDIM);
        float4* dst = (float4*)gs;
        for (int x = tid; x < (4 * DDIM) / 4; x += 640) dst[x] = src[x];
    }
    __syncthreads();

    const int h  = tid % 160;
    const int ks = tid / 160;
    const bool hv = (h < HDIM);
    const int hc = hv ? h : 0;
    float acc1[4], acc2[4];
    float bb = (hv && ks == 0) ? b1[h] : 0.f;
    #pragma unroll
    for (int q = 0; q < 4; ++q) { acc1[q] = bb; acc2[q] = 0.f; }
    const float* W1a = W1 + hc;
    const float* W1b = W1 + DDIM * HDIM + hc;
    const int d0b = ks * 128;
    for (int d0 = d0b; d0 < d0b + 128; d0 += 8) {
        float w1r[8], w2r[8];
        #pragma unroll
        for (int u = 0; u < 8; ++u) {
            w1r[u] = W1a[(d0 + u) * HDIM];
            w2r[u] = W1b[(d0 + u) * HDIM];
        }
        if (!hv) {
            #pragma unroll
            for (int u = 0; u < 8; ++u) { w1r[u] = 0.f; w2r[u] = 0.f; }
        }
        #pragma unroll
        for (int q = 0; q < 4; ++q) {
            const float* gq = gs + q * DDIM + d0;
            float4 ga = *(const float4*)gq;
            float4 gb = *(const float4*)(gq + 4);
            acc1[q] += ga.x * w1r[0] + ga.y * w1r[1] + ga.z * w1r[2] + ga.w * w1r[3]
                     + gb.x * w1r[4] + gb.y * w1r[5] + gb.z * w1r[6] + gb.w * w1r[7];
            acc2[q] += ga.x * w2r[0] + ga.y * w2r[1] + ga.z * w2r[2] + ga.w * w2r[3]
                     + gb.x * w2r[4] + gb.y * w2r[5] + gb.z * w2r[6] + gb.w * w2r[7];
        }
    }
    if (ks > 0) {
        float* r = red + ((ks - 1) * 160 + h) * 8;
        #pragma unroll
        for (int q = 0; q < 4; ++q) { r[q] = acc1[q]; r[4 + q] = acc2[q]; }
    }
    __syncthreads();
    if (ks == 0) {
        #pragma unroll
        for (int s = 0; s < 3; ++s) {
            const float* r = red + (s * 160 + h) * 8;
            #pragma unroll
            for (int q = 0; q < 4; ++q) { acc1[q] += r[q]; acc2[q] += r[4 + q]; }
        }
        #pragma unroll
        for (int q = 0; q < 4; ++q) {
            g_giT[(i0 + q) * HP + h]   = acc1[q];
            g_gjT_T[h * NN + (i0 + q)] = acc2[q];
        }
    }
}

// ---------------------------------------------------------------------------
// Precompute 2: fp16 B-tiles [n][k] pitch 72 halves, hi only.
// ---------------------------------------------------------------------------
__global__ void __launch_bounds__(256) precompute_wsplit(
    const float* __restrict__ W1, const float* __restrict__ W2)
{
    const int bt = blockIdx.x;
    const int tid = threadIdx.x;
    const float* W1c = W1 + 2 * DDIM * HDIM;

    if (bt < 8) {
        const int kt = bt;
        __half* dhi = g_W1hi + kt * TILE_W_HALVES;
        for (int idx = tid; idx < HP * 64; idx += 256) {
            int n = idx >> 6, k = idx & 63;
            int d = kt * 64 + k;
            float val = (n < HDIM) ? W1c[d * HDIM + n] : 0.f;
            dhi[n * 72 + k] = __float2half_rn(val);
        }
    } else {
        const int kt = bt - 8;
        __half* dhi = g_W2hi + kt * TILE_W_HALVES;
        for (int idx = tid; idx < HP * 64; idx += 256) {
            int n = idx >> 6, k = idx & 63;
            int kg = kt * 64 + k;
            float val = (kg < HDIM && n < HDIM) ? W2[kg * HDIM + n] : 0.f;
            dhi[n * 72 + k] = __float2half_rn(val);
        }
    }
}

// ---------------------------------------------------------------------------
// Main kernel. CTA = (i, 128 pairs). grid (2, 1024). 8 warps: wm=wid&3 (M 32),
// wn=wid>>2 (N 80). Stage1 pure fp16 double-buffered; stage2 fp16, K=160.
// ---------------------------------------------------------------------------
__global__ void __launch_bounds__(NTHR, 2) pair_mma_kernel(
    const float* __restrict__ g,  const float* __restrict__ sm,
    const float* __restrict__ b2, const float* __restrict__ W3,
    const float* __restrict__ b3, float* __restrict__ out)
{
    extern __shared__ char smem[];
    const uint32_t sb = smem_u32(smem);
    const int tid = threadIdx.x;
    const int i  = blockIdx.y;
    const int k0 = blockIdx.x * 128;

    // ---- early exit: whole CTA out of window (j_max < 0) ----
    if (i - WWIN + k0 + 127 < 0) {
        if (tid < 128) out[(size_t)i * OUTW + k0 + tid] = 0.f;
        return;
    }

    const int wid = tid >> 5, lid = tid & 31;
    const int wm = wid & 3, wn = wid >> 2;
    const int gq = lid >> 2, t = lid & 3;

    int jrow[2][2];
    #pragma unroll
    for (int mi = 0; mi < 2; ++mi)
        #pragma unroll
        for (int h8 = 0; h8 < 2; ++h8) {
            int p = wm * 32 + mi * 16 + gq + h8 * 8;
            int j = i - WWIN + k0 + p;
            jrow[mi][h8] = min(max(j, 0), NN - 1);
        }

    // ---- accumulators, init with bias terms giT[i][col] + gjT[col][j] ----
    float acc[2][10][4];
    {
        const float* giR = g_giT + i * HP;
        #pragma unroll
        for (int nt = 0; nt < 10; ++nt)
            #pragma unroll
            for (int par = 0; par < 2; ++par) {
                int col = wn * 80 + nt * 8 + 2 * t + par;
                float gic = giR[col];
                const float* gjc = g_gjT_T + col * NN;
                #pragma unroll
                for (int mi = 0; mi < 2; ++mi)
                    #pragma unroll
                    for (int h8 = 0; h8 < 2; ++h8)
                        acc[mi][nt][h8 * 2 + par] = gic + gjc[jrow[mi][h8]];
            }
    }

    // ---- ldmatrix lane offsets ----
    const int mq = lid >> 3, rr = lid & 7;
    uint32_t aOff[2], bOff[5];
    #pragma unroll
    for (int mi = 0; mi < 2; ++mi)
        aOff[mi] = (uint32_t)((wm * 32 + mi * 16 + (mq & 1) * 8 + rr) * 144 + (mq >> 1) * 16);
    #pragma unroll
    for (int ntp = 0; ntp < 5; ++ntp)
        bOff[ntp] = (uint32_t)((wn * 80 + (ntp * 2 + (mq >> 1)) * 8 + rr) * 144 + (mq & 1) * 16);

    // ---- A-prep identity ----
    const int pA = tid >> 1;
    const int sA = tid & 1;
    const int jA = min(max(i - WWIN + k0 + pA, 0), NN - 1);
    const float4* giRow4 = (const float4*)(g + i * DDIM);
    const float4* gjRow4 = (const float4*)(g + jA * DDIM);

    // =================== Stage 1: acc += (gi*gj) @ W1c (fp16) ==============
    {
        const char* src = (const char*)g_W1hi;            // kt=0 tile -> SB1
        for (int x = tid; x < TILE_W_U4; x += NTHR)
            cp16(sb + SB1 + x * 16, src + x * 16);
        CP_COMMIT();
        const int qb = sA * 8;
        char* dst = smem + SA0 + pA * 144 + sA * 64;
        #pragma unroll
        for (int q = 0; q < 8; ++q) {
            float4 a = giRow4[qb + q];
            float4 b = gjRow4[qb + q];
            __half2 h0 = __float22half2_rn(make_float2(a.x * b.x, a.y * b.y));
            __half2 h1 = __float22half2_rn(make_float2(a.z * b.z, a.w * b.w));
            *(uint2*)(dst + q * 8) = make_uint2(*(uint32_t*)&h0, *(uint32_t*)&h1);
        }
        CP_WAIT0();
        __syncthreads();
    }

    for (int kt = 0; kt < 8; ++kt) {
        // cp next B (or prefetch stage2's first W2 tile on the last iter)
        if (kt < 7) {
            const char* src = (const char*)(g_W1hi + (kt + 1) * TILE_W_HALVES);
            uint32_t dstB = sb + (((kt + 1) & 1) ? SB0 : SB1);
            for (int x = tid; x < TILE_W_U4; x += NTHR)
                cp16(dstB + x * 16, src + x * 16);
        } else {
            const char* shi = (const char*)g_W2hi;        // tile0 -> B2B0 (=SB1, free: kt=7 uses SB0)
            for (int x = tid; x < TILE_W_U4; x += NTHR)
                cp16(sb + B2B0 + x * 16, shi + x * 16);
        }
        CP_COMMIT();

        // MMA(kt)
        const uint32_t aB = sb + ((kt & 1) ? SA1 : SA0);
        const uint32_t bB = sb + ((kt & 1) ? SB0 : SB1);
        #pragma unroll
        for (int ks = 0; ks < 4; ++ks) {
            uint32_t ah0[4], ah1[4];
            ldsm4(ah0, aB + aOff[0] + ks * 32);
            ldsm4(ah1, aB + aOff[1] + ks * 32);
            #pragma unroll
            for (int ntp = 0; ntp < 5; ++ntp) {
                uint32_t bf[4];
                ldsm4(bf, bB + bOff[ntp] + ks * 32);
                mma16816(acc[0][2 * ntp],     ah0[0], ah0[1], ah0[2], ah0[3], bf[0], bf[1]);
                mma16816(acc[1][2 * ntp],     ah1[0], ah1[1], ah1[2], ah1[3], bf[0], bf[1]);
                mma16816(acc[0][2 * ntp + 1], ah0[0], ah0[1], ah0[2], ah0[3], bf[2], bf[3]);
                mma16816(acc[1][2 * ntp + 1], ah1[0], ah1[1], ah1[2], ah1[3], bf[2], bf[3]);
            }
        }

        // prep next A
        if (kt < 7) {
            const int qb = (kt + 1) * 16 + sA * 8;
            char* dst = smem + (((kt + 1) & 1) ? SA1 : SA0) + pA * 144 + sA * 64;
            #pragma unroll
            for (int q = 0; q < 8; ++q) {
                float4 a = giRow4[qb + q];
                float4 b = gjRow4[qb + q];
                __half2 h0 = __float22half2_rn(make_float2(a.x * b.x, a.y * b.y));
                __half2 h1 = __float22half2_rn(make_float2(a.z * b.z, a.w * b.w));
                *(uint2*)(dst + q * 8) = make_uint2(*(uint32_t*)&h0, *(uint32_t*)&h1);
            }
        }
        CP_WAIT0();
        __syncthreads();
    }

    // ============ h1 = relu(acc) -> SMEM (single fp16, 3 k-tiles) ==========
    {
        #pragma unroll
        for (int mi = 0; mi < 2; ++mi)
            #pragma unroll
            for (int h8 = 0; h8 < 2; ++h8) {
                int row = wm * 32 + mi * 16 + gq + h8 * 8;
                #pragma unroll
                for (int nt = 0; nt < 10; ++nt) {
                    int col = wn * 80 + nt * 8 + 2 * t;
                    float v0 = fmaxf(acc[mi][nt][h8 * 2 + 0], 0.f);
                    float v1 = fmaxf(acc[mi][nt][h8 * 2 + 1], 0.f);
                    __half2 h = __float22half2_rn(make_float2(v0, v1));
                    int tile = col >> 6;
                    uint32_t off = (uint32_t)(tile * 18432 + row * 144 + (col & 63) * 2);
                    *(uint32_t*)(smem + off) = *(uint32_t*)&h;
                }
            }
    }

    // ---- re-init acc with b2 for stage 2 ----
    #pragma unroll
    for (int nt = 0; nt < 10; ++nt)
        #pragma unroll
        for (int par = 0; par < 2; ++par) {
            int col = wn * 80 + nt * 8 + 2 * t + par;
            float bv = (col < HDIM) ? b2[col] : 0.f;
            #pragma unroll
            for (int mi = 0; mi < 2; ++mi)
                #pragma unroll
                for (int h8 = 0; h8 < 2; ++h8)
                    acc[mi][nt][h8 * 2 + par] = bv;
        }
    __syncthreads();

    // ======== Stage 2: acc += relu(h1) @ W2 (fp16, K=160, dbl-buffered) ====
    for (int kt2 = 0; kt2 < 3; ++kt2) {
        if (kt2 < 2) {
            const char* src = (const char*)(g_W2hi + (kt2 + 1) * TILE_W_HALVES);
            uint32_t dstB = sb + (((kt2 + 1) & 1) ? B2B1 : B2B0);
            for (int x = tid; x < TILE_W_U4; x += NTHR)
                cp16(dstB + x * 16, src + x * 16);
            CP_COMMIT();
        }
        const uint32_t aB2 = sb + kt2 * 18432;
        const uint32_t bB2 = sb + ((kt2 & 1) ? B2B1 : B2B0);
        const int nks = (kt2 == 2) ? 2 : 4;
        for (int ks = 0; ks < nks; ++ks) {
            uint32_t af0[4], af1[4];
            ldsm4(af0, aB2 + aOff[0] + ks * 32);
            ldsm4(af1, aB2 + aOff[1] + ks * 32);
            #pragma unroll
            for (int ntp = 0; ntp < 5; ++ntp) {
                uint32_t bf[4];
                ldsm4(bf, bB2 + bOff[ntp] + ks * 32);
                mma16816(acc[0][2 * ntp],     af0[0], af0[1], af0[2], af0[3], bf[0], bf[1]);
                mma16816(acc[1][2 * ntp],     af1[0], af1[1], af1[2], af1[3], bf[0], bf[1]);
                mma16816(acc[0][2 * ntp + 1], af0[0], af0[1], af0[2], af0[3], bf[2], bf[3]);
                mma16816(acc[1][2 * ntp + 1], af1[0], af1[1], af1[2], af1[3], bf[2], bf[3]);
            }
        }
        CP_WAIT0();
        __syncthreads();
    }

    // =================== Epilogue: relu(acc) @ W3, reduce ==================
    float rsum[2][2] = {{0.f, 0.f}, {0.f, 0.f}};
    #pragma unroll
    for (int nt = 0; nt < 10; ++nt)
        #pragma unroll
        for (int par = 0; par < 2; ++par) {
            int col = wn * 80 + nt * 8 + 2 * t + par;
            float w3 = (col < HDIM) ? W3[col] : 0.f;
            #pragma unroll
            for (int mi = 0; mi < 2; ++mi)
                #pragma unroll
                for (int h8 = 0; h8 < 2; ++h8)
                    rsum[mi][h8] += fmaxf(acc[mi][nt][h8 * 2 + par], 0.f) * w3;
        }
    #pragma unroll
    for (int mi = 0; mi < 2; ++mi)
        #pragma unroll
        for (int h8 = 0; h8 < 2; ++h8) {
            float v = rsum[mi][h8];
            v += __shfl_xor_sync(0xffffffffu, v, 1);
            v += __shfl_xor_sync(0xffffffffu, v, 2);
            rsum[mi][h8] = v;
        }

    float* sred = (float*)(smem + SRED);
    if (wn == 0 && t == 0) {
        #pragma unroll
        for (int mi = 0; mi < 2; ++mi)
            #pragma unroll
            for (int h8 = 0; h8 < 2; ++h8)
                sred[wm * 32 + mi * 16 + gq + h8 * 8] = rsum[mi][h8];
    }
    __syncthreads();
    if (wn == 1 && t == 0) {
        float smi = sm[i];
        float bb3 = b3[0];
        #pragma unroll
        for (int mi = 0; mi < 2; ++mi)
            #pragma unroll
            for (int h8 = 0; h8 < 2; ++h8) {
                int p = wm * 32 + mi * 16 + gq + h8 * 8;
                int k = k0 + p;
                int j = i - WWIN + k;
                float tot = rsum[mi][h8] + sred[p];
                if (k < WWIN) {
                    float val = 0.f;
                    if (j >= 0) val = tot + bb3 + smi + sm[j];
                    out[(size_t)i * OUTW + k] = val;
                } else if (k == WWIN) {
                    out[(size_t)i * OUTW + k] = 0.f;   // epsilon column
                }
            }
    }
}

// ---------------------------------------------------------------------------
extern "C" void kernel_launch(void* const* d_in, const int* in_sizes, int n_in,
                              void* d_out, int out_size)
{
    const float* g  = (const float*)d_in[0];
    const float* sm = (const float*)d_in[1];
    const float* W1 = (const float*)d_in[2];
    const float* b1 = (const float*)d_in[3];
    const float* W2 = (const float*)d_in[4];
    const float* b2 = (const float*)d_in[5];
    const float* W3 = (const float*)d_in[6];
    const float* b3 = (const float*)d_in[7];
    float* out = (float*)d_out;

    cudaFuncSetAttribute(pair_mma_kernel,
                         cudaFuncAttributeMaxDynamicSharedMemorySize, SMEM_TOTAL);

    precompute_gt<<<NN / 4, 640>>>(g, W1, b1);
    precompute_wsplit<<<11, 256>>>(W1, W2);

    dim3 grid(2, NN);
    pair_mma_kernel<<<grid, NTHR, SMEM_TOTAL>>>(g, sm, b2, W3, b3, out);
}

// round 8
// speedup vs baseline: 6.9719x; 1.6021x over previous
#include <cuda_runtime.h>
#include <cuda_fp16.h>
#include <cstdint>

#define NN    1024
#define DDIM  512
#define HDIM  150
#define HP    160
#define WWIN  250
#define OUTW  251
#define NTHR  128
#define MT    64

// ---- dynamic SMEM byte offsets ----
#define SA    0                 // 64*144 = 9216 (single buffer A)
#define SB0   9216              // 152*144 = 21888
#define SB1   31104             // -> 52992
#define SB2   27648             // stage2 W2 tile (overlays dead stage1 B)
#define SRED  52992             // 64 floats
#define SMEM_TOTAL 53248

#define BROWS 152
#define TILE_B_BYTES (BROWS * 144)      // 21888
#define TILE_B_U4    (TILE_B_BYTES/16)  // 1368
#define TILE_W_HALVES (BROWS * 72)      // 10944

// ---------------------------------------------------------------------------
// Device scratch
// ---------------------------------------------------------------------------
__device__ float g_giT[NN * HP];      // g@W1a + b1, [i][h], zero pad h>=150
__device__ float g_gjT_T[HP * NN];    // (g@W1b)^T, [h][i], zero pad
__device__ __align__(16) __half g_h[NN * DDIM];   // fp16 copy of g
__device__ __align__(16) __half g_W1hi[8 * TILE_W_HALVES];
__device__ __align__(16) __half g_W2hi[3 * TILE_W_HALVES];

// ---------------------------------------------------------------------------
// Helpers
// ---------------------------------------------------------------------------
__device__ __forceinline__ uint32_t smem_u32(const void* p) {
    uint32_t a;
    asm("{ .reg .u64 t; cvta.to.shared.u64 t, %1; cvt.u32.u64 %0, t; }"
        : "=r"(a) : "l"(p));
    return a;
}

__device__ __forceinline__ void cp16(uint32_t s, const void* g) {
    asm volatile("{\n\t.reg .u64 gp;\n\tcvta.to.global.u64 gp, %1;\n\t"
                 "cp.async.cg.shared.global [%0], [gp], 16;\n\t}"
                 :: "r"(s), "l"(g) : "memory");
}
#define CP_COMMIT() asm volatile("cp.async.commit_group;" ::: "memory")
#define CP_WAIT0()  asm volatile("cp.async.wait_group 0;" ::: "memory")

__device__ __forceinline__ void ldsm4(uint32_t* r, uint32_t addr) {
    asm volatile("ldmatrix.sync.aligned.m8n8.x4.shared.b16 {%0,%1,%2,%3}, [%4];"
        : "=r"(r[0]), "=r"(r[1]), "=r"(r[2]), "=r"(r[3]) : "r"(addr));
}

__device__ __forceinline__ void mma16816(float* c,
    uint32_t a0, uint32_t a1, uint32_t a2, uint32_t a3,
    uint32_t b0, uint32_t b1)
{
    asm volatile(
        "mma.sync.aligned.m16n8k16.row.col.f32.f16.f16.f32 "
        "{%0,%1,%2,%3}, {%4,%5,%6,%7}, {%8,%9}, {%0,%1,%2,%3};"
        : "+f"(c[0]), "+f"(c[1]), "+f"(c[2]), "+f"(c[3])
        : "r"(a0), "r"(a1), "r"(a2), "r"(a3), "r"(b0), "r"(b1));
}

__device__ __forceinline__ uint4 hmul_u4(uint4 x, uint4 y) {
    __half2* xa = (__half2*)&x;
    __half2* ya = (__half2*)&y;
    uint4 r;
    __half2* ra = (__half2*)&r;
    ra[0] = __hmul2(xa[0], ya[0]);
    ra[1] = __hmul2(xa[1], ya[1]);
    ra[2] = __hmul2(xa[2], ya[2]);
    ra[3] = __hmul2(xa[3], ya[3]);
    return r;
}

// ---------------------------------------------------------------------------
// Precompute 1: giT = g@W1a + b1, gjT_T = (g@W1b)^T (fp32), plus g_h = fp16(g).
// 512 blocks x 640 thr: 2 rows/block, h = tid%160, ks = tid/160 (4-way K-split).
// ---------------------------------------------------------------------------
__global__ void __launch_bounds__(640) precompute_gt(
    const float* __restrict__ g, const float* __restrict__ W1,
    const float* __restrict__ b1)
{
    __shared__ float gs[2 * DDIM];
    __shared__ float red[3 * 160 * 4];
    const int i0 = blockIdx.x * 2;
    const int tid = threadIdx.x;
    {
        const float4* src = (const float4*)(g + i0 * DDIM);
        float4* dst = (float4*)gs;
        if (tid < (2 * DDIM) / 4) dst[tid] = src[tid];
    }
    __syncthreads();
    // fp16 copy of these 2 rows
    for (int x = tid; x < 2 * DDIM; x += 640)
        g_h[i0 * DDIM + x] = __float2half_rn(gs[x]);

    const int h  = tid % 160;
    const int ks = tid / 160;
    const bool hv = (h < HDIM);
    const int hc = hv ? h : 0;
    float acc1[2], acc2[2];
    float bb = (hv && ks == 0) ? b1[h] : 0.f;
    #pragma unroll
    for (int q = 0; q < 2; ++q) { acc1[q] = bb; acc2[q] = 0.f; }
    const float* W1a = W1 + hc;
    const float* W1b = W1 + DDIM * HDIM + hc;
    const int d0b = ks * 128;
    for (int d0 = d0b; d0 < d0b + 128; d0 += 8) {
        float w1r[8], w2r[8];
        #pragma unroll
        for (int u = 0; u < 8; ++u) {
            w1r[u] = W1a[(d0 + u) * HDIM];
            w2r[u] = W1b[(d0 + u) * HDIM];
        }
        if (!hv) {
            #pragma unroll
            for (int u = 0; u < 8; ++u) { w1r[u] = 0.f; w2r[u] = 0.f; }
        }
        #pragma unroll
        for (int q = 0; q < 2; ++q) {
            const float* gq = gs + q * DDIM + d0;
            float4 ga = *(const float4*)gq;
            float4 gb = *(const float4*)(gq + 4);
            acc1[q] += ga.x * w1r[0] + ga.y * w1r[1] + ga.z * w1r[2] + ga.w * w1r[3]
                     + gb.x * w1r[4] + gb.y * w1r[5] + gb.z * w1r[6] + gb.w * w1r[7];
            acc2[q] += ga.x * w2r[0] + ga.y * w2r[1] + ga.z * w2r[2] + ga.w * w2r[3]
                     + gb.x * w2r[4] + gb.y * w2r[5] + gb.z * w2r[6] + gb.w * w2r[7];
        }
    }
    if (ks > 0) {
        float* r = red + ((ks - 1) * 160 + h) * 4;
        r[0] = acc1[0]; r[1] = acc1[1]; r[2] = acc2[0]; r[3] = acc2[1];
    }
    __syncthreads();
    if (ks == 0) {
        #pragma unroll
        for (int s = 0; s < 3; ++s) {
            const float* r = red + (s * 160 + h) * 4;
            acc1[0] += r[0]; acc1[1] += r[1]; acc2[0] += r[2]; acc2[1] += r[3];
        }
        #pragma unroll
        for (int q = 0; q < 2; ++q) {
            g_giT[(i0 + q) * HP + h]   = acc1[q];
            g_gjT_T[h * NN + (i0 + q)] = acc2[q];
        }
    }
}

// ---------------------------------------------------------------------------
// Precompute 2: fp16 B-tiles [n=0..151][k=0..63] pitch 72 halves.
// ---------------------------------------------------------------------------
__global__ void __launch_bounds__(256) precompute_wsplit(
    const float* __restrict__ W1, const float* __restrict__ W2)
{
    const int bt = blockIdx.x;
    const int tid = threadIdx.x;
    const float* W1c = W1 + 2 * DDIM * HDIM;

    if (bt < 8) {
        const int kt = bt;
        __half* dhi = g_W1hi + kt * TILE_W_HALVES;
        for (int idx = tid; idx < BROWS * 64; idx += 256) {
            int n = idx >> 6, k = idx & 63;
            int d = kt * 64 + k;
            float val = (n < HDIM) ? W1c[d * HDIM + n] : 0.f;
            dhi[n * 72 + k] = __float2half_rn(val);
        }
    } else {
        const int kt = bt - 8;
        __half* dhi = g_W2hi + kt * TILE_W_HALVES;
        for (int idx = tid; idx < BROWS * 64; idx += 256) {
            int n = idx >> 6, k = idx & 63;
            int kg = kt * 64 + k;
            float val = (kg < HDIM && n < HDIM) ? W2[kg * HDIM + n] : 0.f;
            dhi[n * 72 + k] = __float2half_rn(val);
        }
    }
}

// ---------------------------------------------------------------------------
// Main kernel. CTA = (i, 64 pairs). grid (4, 1024). 4 warps: wm=wid&1 (M 32),
// wn=wid>>1 (N 80). A single-buffered (computed), B double-buffered, N=152.
// ---------------------------------------------------------------------------
__global__ void __launch_bounds__(NTHR, 4) pair_mma_kernel(
    const float* __restrict__ sm, const float* __restrict__ b2,
    const float* __restrict__ W3, const float* __restrict__ b3,
    float* __restrict__ out)
{
    extern __shared__ char smem[];
    const uint32_t sb = smem_u32(smem);
    const int tid = threadIdx.x;
    const int i  = blockIdx.y;
    const int k0 = blockIdx.x * MT;

    // ---- early exit: whole CTA out of window ----
    if (i - WWIN + k0 + (MT - 1) < 0) {
        if (tid < MT) out[(size_t)i * OUTW + k0 + tid] = 0.f;
        return;
    }

    const int wid = tid >> 5, lid = tid & 31;
    const int wm = wid & 1, wn = wid >> 1;
    const int gq = lid >> 2, t = lid & 3;
    const bool trim = (wn == 1);   // this warp owns cols 80..159; tile19 dead

    int jrow[2][2];
    #pragma unroll
    for (int mi = 0; mi < 2; ++mi)
        #pragma unroll
        for (int h8 = 0; h8 < 2; ++h8) {
            int p = wm * 32 + mi * 16 + gq + h8 * 8;
            int j = i - WWIN + k0 + p;
            jrow[mi][h8] = min(max(j, 0), NN - 1);
        }

    // ---- accumulators, init with bias terms giT[i][col] + gjT[col][j] ----
    float acc[2][10][4];
    {
        const float* giR = g_giT + i * HP;
        #pragma unroll
        for (int nt = 0; nt < 10; ++nt)
            #pragma unroll
            for (int par = 0; par < 2; ++par) {
                int col = wn * 80 + nt * 8 + 2 * t + par;
                float gic = giR[col];
                const float* gjc = g_gjT_T + col * NN;
                #pragma unroll
                for (int mi = 0; mi < 2; ++mi)
                    #pragma unroll
                    for (int h8 = 0; h8 < 2; ++h8)
                        acc[mi][nt][h8 * 2 + par] = gic + gjc[jrow[mi][h8]];
            }
    }

    // ---- ldmatrix lane offsets ----
    const int mq = lid >> 3, rr = lid & 7;
    uint32_t aOff[2], bOff[5];
    #pragma unroll
    for (int mi = 0; mi < 2; ++mi)
        aOff[mi] = (uint32_t)((wm * 32 + mi * 16 + (mq & 1) * 8 + rr) * 144 + (mq >> 1) * 16);
    #pragma unroll
    for (int ntp = 0; ntp < 5; ++ntp) {
        int rowb = wn * 80 + (ntp * 2 + (mq >> 1)) * 8 + rr;
        if (rowb > 151) rowb = 151;           // clamp dead tile-19 rows (values unused)
        bOff[ntp] = (uint32_t)(rowb * 144 + (mq & 1) * 16);
    }

    // ---- A-prep identity: row pA, half sA ----
    const int pA = tid >> 1;
    const int sA = tid & 1;
    const int jA = min(max(i - WWIN + k0 + pA, 0), NN - 1);
    const uint4* giRow = (const uint4*)(g_h + (size_t)i  * DDIM) + sA * 4;
    const uint4* gjRow = (const uint4*)(g_h + (size_t)jA * DDIM) + sA * 4;
    uint4* aDst = (uint4*)(smem + SA + pA * 144 + sA * 64);

    // =================== Stage 1: acc += (gi*gj) @ W1c (fp16) ==============
    {
        const char* src = (const char*)g_W1hi;       // kt=0 -> SB0
        for (int x = tid; x < TILE_B_U4; x += NTHR)
            cp16(sb + SB0 + x * 16, src + x * 16);
        CP_COMMIT();
        #pragma unroll
        for (int q = 0; q < 4; ++q)
            aDst[q] = hmul_u4(giRow[q], gjRow[q]);   // kt=0 cols
        CP_WAIT0();
        __syncthreads();
    }

    for (int kt = 0; kt < 8; ++kt) {
        if (kt < 7) {
            const char* src = (const char*)(g_W1hi + (kt + 1) * TILE_W_HALVES);
            uint32_t dstB = sb + (((kt + 1) & 1) ? SB1 : SB0);
            for (int x = tid; x < TILE_B_U4; x += NTHR)
                cp16(dstB + x * 16, src + x * 16);
            CP_COMMIT();
        }

        const uint32_t bB = sb + ((kt & 1) ? SB1 : SB0);
        #pragma unroll
        for (int ks = 0; ks < 4; ++ks) {
            uint32_t ah0[4], ah1[4];
            ldsm4(ah0, sb + SA + aOff[0] + ks * 32);
            ldsm4(ah1, sb + SA + aOff[1] + ks * 32);
            #pragma unroll
            for (int ntp = 0; ntp < 5; ++ntp) {
                uint32_t bf[4];
                ldsm4(bf, bB + bOff[ntp] + ks * 32);
                mma16816(acc[0][2 * ntp],     ah0[0], ah0[1], ah0[2], ah0[3], bf[0], bf[1]);
                mma16816(acc[1][2 * ntp],     ah1[0], ah1[1], ah1[2], ah1[3], bf[0], bf[1]);
                if (ntp < 4 || !trim) {
                    mma16816(acc[0][2 * ntp + 1], ah0[0], ah0[1], ah0[2], ah0[3], bf[2], bf[3]);
                    mma16816(acc[1][2 * ntp + 1], ah1[0], ah1[1], ah1[2], ah1[3], bf[2], bf[3]);
                }
            }
        }
        __syncthreads();             // A + B(kt) consumed by all warps

        if (kt < 7) {
            const uint4* gi = giRow + (kt + 1) * 8;
            const uint4* gj = gjRow + (kt + 1) * 8;
            #pragma unroll
            for (int q = 0; q < 4; ++q)
                aDst[q] = hmul_u4(gi[q], gj[q]);
        }
        CP_WAIT0();
        __syncthreads();
    }

    // ============ h1 = relu(acc) -> SMEM (single fp16, 3 k-tiles) ==========
    {
        #pragma unroll
        for (int mi = 0; mi < 2; ++mi)
            #pragma unroll
            for (int h8 = 0; h8 < 2; ++h8) {
                int row = wm * 32 + mi * 16 + gq + h8 * 8;
                #pragma unroll
                for (int nt = 0; nt < 10; ++nt) {
                    int col = wn * 80 + nt * 8 + 2 * t;
                    float v0 = fmaxf(acc[mi][nt][h8 * 2 + 0], 0.f);
                    float v1 = fmaxf(acc[mi][nt][h8 * 2 + 1], 0.f);
                    __half2 h = __float22half2_rn(make_float2(v0, v1));
                    int tile = col >> 6;
                    uint32_t off = (uint32_t)(tile * 9216 + row * 144 + (col & 63) * 2);
                    *(uint32_t*)(smem + off) = *(uint32_t*)&h;
                }
            }
    }

    // ---- re-init acc with b2 for stage 2 ----
    #pragma unroll
    for (int nt = 0; nt < 10; ++nt)
        #pragma unroll
        for (int par = 0; par < 2; ++par) {
            int col = wn * 80 + nt * 8 + 2 * t + par;
            float bv = (col < HDIM) ? b2[col] : 0.f;
            #pragma unroll
            for (int mi = 0; mi < 2; ++mi)
                #pragma unroll
                for (int h8 = 0; h8 < 2; ++h8)
                    acc[mi][nt][h8 * 2 + par] = bv;
        }
    __syncthreads();

    // ======== Stage 2: acc += relu(h1) @ W2 (fp16, K=160) ==================
    for (int kt2 = 0; kt2 < 3; ++kt2) {
        {
            const char* src = (const char*)(g_W2hi + kt2 * TILE_W_HALVES);
            for (int x = tid; x < TILE_B_U4; x += NTHR)
                cp16(sb + SB2 + x * 16, src + x * 16);
            CP_COMMIT();
            CP_WAIT0();
            __syncthreads();
        }
        const uint32_t aB2 = sb + kt2 * 9216;
        const int nks = (kt2 == 2) ? 2 : 4;
        for (int ks = 0; ks < nks; ++ks) {
            uint32_t af0[4], af1[4];
            ldsm4(af0, aB2 + aOff[0] + ks * 32);
            ldsm4(af1, aB2 + aOff[1] + ks * 32);
            #pragma unroll
            for (int ntp = 0; ntp < 5; ++ntp) {
                uint32_t bf[4];
                ldsm4(bf, sb + SB2 + bOff[ntp] + ks * 32);
                mma16816(acc[0][2 * ntp],     af0[0], af0[1], af0[2], af0[3], bf[0], bf[1]);
                mma16816(acc[1][2 * ntp],     af1[0], af1[1], af1[2], af1[3], bf[0], bf[1]);
                if (ntp < 4 || !trim) {
                    mma16816(acc[0][2 * ntp + 1], af0[0], af0[1], af0[2], af0[3], bf[2], bf[3]);
                    mma16816(acc[1][2 * ntp + 1], af1[0], af1[1], af1[2], af1[3], bf[2], bf[3]);
                }
            }
        }
        __syncthreads();
    }

    // =================== Epilogue: relu(acc) @ W3, reduce ==================
    float rsum[2][2] = {{0.f, 0.f}, {0.f, 0.f}};
    #pragma unroll
    for (int nt = 0; nt < 10; ++nt)
        #pragma unroll
        for (int par = 0; par < 2; ++par) {
            int col = wn * 80 + nt * 8 + 2 * t + par;
            float w3 = (col < HDIM) ? W3[col] : 0.f;
            #pragma unroll
            for (int mi = 0; mi < 2; ++mi)
                #pragma unroll
                for (int h8 = 0; h8 < 2; ++h8)
                    rsum[mi][h8] += fmaxf(acc[mi][nt][h8 * 2 + par], 0.f) * w3;
        }
    #pragma unroll
    for (int mi = 0; mi < 2; ++mi)
        #pragma unroll
        for (int h8 = 0; h8 < 2; ++h8) {
            float v = rsum[mi][h8];
            v += __shfl_xor_sync(0xffffffffu, v, 1);
            v += __shfl_xor_sync(0xffffffffu, v, 2);
            rsum[mi][h8] = v;
        }

    float* sred = (float*)(smem + SRED);
    if (wn == 0 && t == 0) {
        #pragma unroll
        for (int mi = 0; mi < 2; ++mi)
            #pragma unroll
            for (int h8 = 0; h8 < 2; ++h8)
                sred[wm * 32 + mi * 16 + gq + h8 * 8] = rsum[mi][h8];
    }
    __syncthreads();
    if (wn == 1 && t == 0) {
        float smi = sm[i];
        float bb3 = b3[0];
        #pragma unroll
        for (int mi = 0; mi < 2; ++mi)
            #pragma unroll
            for (int h8 = 0; h8 < 2; ++h8) {
                int p = wm * 32 + mi * 16 + gq + h8 * 8;
                int k = k0 + p;
                int j = i - WWIN + k;
                float tot = rsum[mi][h8] + sred[p];
                if (k < WWIN) {
                    float val = 0.f;
                    if (j >= 0) val = tot + bb3 + smi + sm[j];
                    out[(size_t)i * OUTW + k] = val;
                } else if (k == WWIN) {
                    out[(size_t)i * OUTW + k] = 0.f;   // epsilon column
                }
            }
    }
}

// ---------------------------------------------------------------------------
extern "C" void kernel_launch(void* const* d_in, const int* in_sizes, int n_in,
                              void* d_out, int out_size)
{
    const float* g  = (const float*)d_in[0];
    const float* sm = (const float*)d_in[1];
    const float* W1 = (const float*)d_in[2];
    const float* b1 = (const float*)d_in[3];
    const float* W2 = (const float*)d_in[4];
    const float* b2 = (const float*)d_in[5];
    const float* W3 = (const float*)d_in[6];
    const float* b3 = (const float*)d_in[7];
    float* out = (float*)d_out;

    cudaFuncSetAttribute(pair_mma_kernel,
                         cudaFuncAttributeMaxDynamicSharedMemorySize, SMEM_TOTAL);

    precompute_gt<<<NN / 2, 640>>>(g, W1, b1);
    precompute_wsplit<<<11, 256>>>(W1, W2);

    dim3 grid(4, NN);
    pair_mma_kernel<<<grid, NTHR, SMEM_TOTAL>>>(sm, b2, W3, b3, out);
}

// round 9
// speedup vs baseline: 7.4364x; 1.0666x over previous
#include <cuda_runtime.h>
#include <cuda_fp16.h>
#include <cstdint>

#define NN    1024
#define DDIM  512
#define HDIM  150
#define HP    160
#define WWIN  250
#define OUTW  251
#define NTHR  128
#define MT    64

// ---- dynamic SMEM byte offsets (main kernel) ----
// Stage1: A=0..9216, B buffers: SB0=9216..31104, SB1=31104..52992
// Parity: bB(kt) = (kt&1) ? SB0 : SB1  (kt=7 -> SB0, frees SB1 for W2 prefetch)
// Stage2: h1 tiles at 0 / 9216 / 18432 ; W2 tile at SB2=31104
#define SA    0
#define SB0   9216
#define SB1   31104
#define SB2   31104
#define SRED  52992
#define SMEM_TOTAL 53248

#define BROWS 152
#define TILE_B_BYTES (BROWS * 144)      // 21888
#define TILE_B_U4    (TILE_B_BYTES/16)  // 1368
#define TILE_W_HALVES (BROWS * 72)      // 10944

// ---------------------------------------------------------------------------
// Device scratch
// ---------------------------------------------------------------------------
__device__ float g_giT[NN * HP];      // g@W1a + b1, [i][h], zero pad h>=150
__device__ float g_gjT_T[HP * NN];    // (g@W1b)^T, [h][i], zero pad
__device__ __align__(16) __half g_h[NN * DDIM];   // fp16 copy of g
__device__ __align__(16) __half g_W1hi[8 * TILE_W_HALVES];
__device__ __align__(16) __half g_W2hi[3 * TILE_W_HALVES];

// ---------------------------------------------------------------------------
// Helpers
// ---------------------------------------------------------------------------
__device__ __forceinline__ uint32_t smem_u32(const void* p) {
    uint32_t a;
    asm("{ .reg .u64 t; cvta.to.shared.u64 t, %1; cvt.u32.u64 %0, t; }"
        : "=r"(a) : "l"(p));
    return a;
}

__device__ __forceinline__ void cp16(uint32_t s, const void* g) {
    asm volatile("{\n\t.reg .u64 gp;\n\tcvta.to.global.u64 gp, %1;\n\t"
                 "cp.async.cg.shared.global [%0], [gp], 16;\n\t}"
                 :: "r"(s), "l"(g) : "memory");
}
#define CP_COMMIT() asm volatile("cp.async.commit_group;" ::: "memory")
#define CP_WAIT0()  asm volatile("cp.async.wait_group 0;" ::: "memory")

__device__ __forceinline__ void ldsm4(uint32_t* r, uint32_t addr) {
    asm volatile("ldmatrix.sync.aligned.m8n8.x4.shared.b16 {%0,%1,%2,%3}, [%4];"
        : "=r"(r[0]), "=r"(r[1]), "=r"(r[2]), "=r"(r[3]) : "r"(addr));
}

__device__ __forceinline__ void mma16816(float* c,
    uint32_t a0, uint32_t a1, uint32_t a2, uint32_t a3,
    uint32_t b0, uint32_t b1)
{
    asm volatile(
        "mma.sync.aligned.m16n8k16.row.col.f32.f16.f16.f32 "
        "{%0,%1,%2,%3}, {%4,%5,%6,%7}, {%8,%9}, {%0,%1,%2,%3};"
        : "+f"(c[0]), "+f"(c[1]), "+f"(c[2]), "+f"(c[3])
        : "r"(a0), "r"(a1), "r"(a2), "r"(a3), "r"(b0), "r"(b1));
}

__device__ __forceinline__ uint4 hmul_u4(uint4 x, uint4 y) {
    __half2* xa = (__half2*)&x;
    __half2* ya = (__half2*)&y;
    uint4 r;
    __half2* ra = (__half2*)&r;
    ra[0] = __hmul2(xa[0], ya[0]);
    ra[1] = __hmul2(xa[1], ya[1]);
    ra[2] = __hmul2(xa[2], ya[2]);
    ra[3] = __hmul2(xa[3], ya[3]);
    return r;
}

// ---------------------------------------------------------------------------
// Merged precompute. Blocks 0..255: giT/gjT_T/g_h (4 rows each, 640 thr,
// h = tid%160, ks = tid/160 4-way K-split + SMEM reduce).
// Blocks 256..266: fp16 weight B-tiles (W1c: 8 tiles, W2: 3 tiles).
// ---------------------------------------------------------------------------
__global__ void __launch_bounds__(640) precompute_all(
    const float* __restrict__ g, const float* __restrict__ W1,
    const float* __restrict__ b1, const float* __restrict__ W2)
{
    const int tid = threadIdx.x;

    if (blockIdx.x >= 256) {
        // ---- weight split path ----
        const int bt = blockIdx.x - 256;
        const float* W1c = W1 + 2 * DDIM * HDIM;
        if (bt < 8) {
            __half* dhi = g_W1hi + bt * TILE_W_HALVES;
            for (int idx = tid; idx < BROWS * 64; idx += 640) {
                int n = idx >> 6, k = idx & 63;
                int d = bt * 64 + k;
                float val = (n < HDIM) ? W1c[d * HDIM + n] : 0.f;
                dhi[n * 72 + k] = __float2half_rn(val);
            }
        } else {
            const int kt = bt - 8;
            __half* dhi = g_W2hi + kt * TILE_W_HALVES;
            for (int idx = tid; idx < BROWS * 64; idx += 640) {
                int n = idx >> 6, k = idx & 63;
                int kg = kt * 64 + k;
                float val = (kg < HDIM && n < HDIM) ? W2[kg * HDIM + n] : 0.f;
                dhi[n * 72 + k] = __float2half_rn(val);
            }
        }
        return;
    }

    // ---- giT / gjT path (4 rows per block) ----
    __shared__ float gs[4 * DDIM];
    __shared__ float red[3 * 160 * 8];
    const int i0 = blockIdx.x * 4;
    {
        const float4* src = (const float4*)(g + i0 * DDIM);
        float4* dst = (float4*)gs;
        for (int x = tid; x < (4 * DDIM) / 4; x += 640) dst[x] = src[x];
    }
    __syncthreads();
    // fp16 copy of these 4 rows
    for (int x = tid; x < 4 * DDIM; x += 640)
        g_h[i0 * DDIM + x] = __float2half_rn(gs[x]);

    const int h  = tid % 160;
    const int ks = tid / 160;
    const bool hv = (h < HDIM);
    const int hc = hv ? h : 0;
    float acc1[4], acc2[4];
    float bb = (hv && ks == 0) ? b1[h] : 0.f;
    #pragma unroll
    for (int q = 0; q < 4; ++q) { acc1[q] = bb; acc2[q] = 0.f; }
    const float* W1a = W1 + hc;
    const float* W1b = W1 + DDIM * HDIM + hc;
    const int d0b = ks * 128;
    for (int d0 = d0b; d0 < d0b + 128; d0 += 8) {
        float w1r[8], w2r[8];
        #pragma unroll
        for (int u = 0; u < 8; ++u) {
            w1r[u] = W1a[(d0 + u) * HDIM];
            w2r[u] = W1b[(d0 + u) * HDIM];
        }
        if (!hv) {
            #pragma unroll
            for (int u = 0; u < 8; ++u) { w1r[u] = 0.f; w2r[u] = 0.f; }
        }
        #pragma unroll
        for (int q = 0; q < 4; ++q) {
            const float* gq = gs + q * DDIM + d0;
            float4 ga = *(const float4*)gq;
            float4 gb = *(const float4*)(gq + 4);
            acc1[q] += ga.x * w1r[0] + ga.y * w1r[1] + ga.z * w1r[2] + ga.w * w1r[3]
                     + gb.x * w1r[4] + gb.y * w1r[5] + gb.z * w1r[6] + gb.w * w1r[7];
            acc2[q] += ga.x * w2r[0] + ga.y * w2r[1] + ga.z * w2r[2] + ga.w * w2r[3]
                     + gb.x * w2r[4] + gb.y * w2r[5] + gb.z * w2r[6] + gb.w * w2r[7];
        }
    }
    if (ks > 0) {
        float* r = red + ((ks - 1) * 160 + h) * 8;
        #pragma unroll
        for (int q = 0; q < 4; ++q) { r[q] = acc1[q]; r[4 + q] = acc2[q]; }
    }
    __syncthreads();
    if (ks == 0) {
        #pragma unroll
        for (int s = 0; s < 3; ++s) {
            const float* r = red + (s * 160 + h) * 8;
            #pragma unroll
            for (int q = 0; q < 4; ++q) { acc1[q] += r[q]; acc2[q] += r[4 + q]; }
        }
        #pragma unroll
        for (int q = 0; q < 4; ++q) {
            g_giT[(i0 + q) * HP + h]   = acc1[q];
            g_gjT_T[h * NN + (i0 + q)] = acc2[q];
        }
    }
}

// ---------------------------------------------------------------------------
// Main kernel. CTA = (i, 64 pairs). grid (4, 1024). 4 warps: wm=wid&1 (M 32),
// wn=wid>>1 (N 80). A single-buffered, B double-buffered, N=152.
// ---------------------------------------------------------------------------
__global__ void __launch_bounds__(NTHR, 4) pair_mma_kernel(
    const float* __restrict__ sm, const float* __restrict__ b2,
    const float* __restrict__ W3, const float* __restrict__ b3,
    float* __restrict__ out)
{
    extern __shared__ char smem[];
    const uint32_t sb = smem_u32(smem);
    const int tid = threadIdx.x;
    const int i  = blockIdx.y;
    const int k0 = blockIdx.x * MT;

    // ---- early exit: whole CTA out of window ----
    if (i - WWIN + k0 + (MT - 1) < 0) {
        if (tid < MT) out[(size_t)i * OUTW + k0 + tid] = 0.f;
        return;
    }

    const int wid = tid >> 5, lid = tid & 31;
    const int wm = wid & 1, wn = wid >> 1;
    const int gq = lid >> 2, t = lid & 3;
    const bool trim = (wn == 1);   // this warp owns cols 80..159; tile19 dead

    int jrow[2][2];
    #pragma unroll
    for (int mi = 0; mi < 2; ++mi)
        #pragma unroll
        for (int h8 = 0; h8 < 2; ++h8) {
            int p = wm * 32 + mi * 16 + gq + h8 * 8;
            int j = i - WWIN + k0 + p;
            jrow[mi][h8] = min(max(j, 0), NN - 1);
        }

    // ---- accumulators, init with bias terms giT[i][col] + gjT[col][j] ----
    float acc[2][10][4];
    {
        const float* giR = g_giT + i * HP;
        #pragma unroll
        for (int nt = 0; nt < 10; ++nt)
            #pragma unroll
            for (int par = 0; par < 2; ++par) {
                int col = wn * 80 + nt * 8 + 2 * t + par;
                float gic = giR[col];
                const float* gjc = g_gjT_T + col * NN;
                #pragma unroll
                for (int mi = 0; mi < 2; ++mi)
                    #pragma unroll
                    for (int h8 = 0; h8 < 2; ++h8)
                        acc[mi][nt][h8 * 2 + par] = gic + gjc[jrow[mi][h8]];
            }
    }

    // ---- ldmatrix lane offsets ----
    const int mq = lid >> 3, rr = lid & 7;
    uint32_t aOff[2], bOff[5];
    #pragma unroll
    for (int mi = 0; mi < 2; ++mi)
        aOff[mi] = (uint32_t)((wm * 32 + mi * 16 + (mq & 1) * 8 + rr) * 144 + (mq >> 1) * 16);
    #pragma unroll
    for (int ntp = 0; ntp < 5; ++ntp) {
        int rowb = wn * 80 + (ntp * 2 + (mq >> 1)) * 8 + rr;
        if (rowb > 151) rowb = 151;           // clamp dead tile-19 rows (values unused)
        bOff[ntp] = (uint32_t)(rowb * 144 + (mq & 1) * 16);
    }

    // ---- A-prep identity: row pA, half sA ----
    const int pA = tid >> 1;
    const int sA = tid & 1;
    const int jA = min(max(i - WWIN + k0 + pA, 0), NN - 1);
    const uint4* giRow = (const uint4*)(g_h + (size_t)i  * DDIM) + sA * 4;
    const uint4* gjRow = (const uint4*)(g_h + (size_t)jA * DDIM) + sA * 4;
    uint4* aDst = (uint4*)(smem + SA + pA * 144 + sA * 64);

    // =================== Stage 1: acc += (gi*gj) @ W1c (fp16) ==============
    {
        const char* src = (const char*)g_W1hi;       // kt=0 -> SB1 (parity: even->SB1)
        for (int x = tid; x < TILE_B_U4; x += NTHR)
            cp16(sb + SB1 + x * 16, src + x * 16);
        CP_COMMIT();
        #pragma unroll
        for (int q = 0; q < 4; ++q)
            aDst[q] = hmul_u4(giRow[q], gjRow[q]);   // kt=0 cols
        CP_WAIT0();
        __syncthreads();
    }

    for (int kt = 0; kt < 8; ++kt) {
        if (kt < 7) {
            const char* src = (const char*)(g_W1hi + (kt + 1) * TILE_W_HALVES);
            uint32_t dstB = sb + (((kt + 1) & 1) ? SB0 : SB1);
            for (int x = tid; x < TILE_B_U4; x += NTHR)
                cp16(dstB + x * 16, src + x * 16);
            CP_COMMIT();
        } else {
            // kt=7 consumes SB0; SB1 region is dead -> prefetch W2 tile 0 there
            const char* src = (const char*)g_W2hi;
            for (int x = tid; x < TILE_B_U4; x += NTHR)
                cp16(sb + SB2 + x * 16, src + x * 16);
            CP_COMMIT();
        }

        const uint32_t bB = sb + ((kt & 1) ? SB0 : SB1);
        #pragma unroll
        for (int ks = 0; ks < 4; ++ks) {
            uint32_t ah0[4], ah1[4];
            ldsm4(ah0, sb + SA + aOff[0] + ks * 32);
            ldsm4(ah1, sb + SA + aOff[1] + ks * 32);
            #pragma unroll
            for (int ntp = 0; ntp < 5; ++ntp) {
                uint32_t bf[4];
                ldsm4(bf, bB + bOff[ntp] + ks * 32);
                mma16816(acc[0][2 * ntp],     ah0[0], ah0[1], ah0[2], ah0[3], bf[0], bf[1]);
                mma16816(acc[1][2 * ntp],     ah1[0], ah1[1], ah1[2], ah1[3], bf[0], bf[1]);
                if (ntp < 4 || !trim) {
                    mma16816(acc[0][2 * ntp + 1], ah0[0], ah0[1], ah0[2], ah0[3], bf[2], bf[3]);
                    mma16816(acc[1][2 * ntp + 1], ah1[0], ah1[1], ah1[2], ah1[3], bf[2], bf[3]);
                }
            }
        }
        __syncthreads();             // A + B(kt) consumed by all warps

        if (kt < 7) {
            const uint4* gi = giRow + (kt + 1) * 8;
            const uint4* gj = gjRow + (kt + 1) * 8;
            #pragma unroll
            for (int q = 0; q < 4; ++q)
                aDst[q] = hmul_u4(gi[q], gj[q]);
        }
        CP_WAIT0();
        __syncthreads();
    }

    // ============ h1 = relu(acc) -> SMEM (single fp16, 3 k-tiles) ==========
    {
        #pragma unroll
        for (int mi = 0; mi < 2; ++mi)
            #pragma unroll
            for (int h8 = 0; h8 < 2; ++h8) {
                int row = wm * 32 + mi * 16 + gq + h8 * 8;
                #pragma unroll
                for (int nt = 0; nt < 10; ++nt) {
                    int col = wn * 80 + nt * 8 + 2 * t;
                    float v0 = fmaxf(acc[mi][nt][h8 * 2 + 0], 0.f);
                    float v1 = fmaxf(acc[mi][nt][h8 * 2 + 1], 0.f);
                    __half2 h = __float22half2_rn(make_float2(v0, v1));
                    int tile = col >> 6;
                    uint32_t off = (uint32_t)(tile * 9216 + row * 144 + (col & 63) * 2);
                    *(uint32_t*)(smem + off) = *(uint32_t*)&h;
                }
            }
    }

    // ---- re-init acc with b2 for stage 2 ----
    #pragma unroll
    for (int nt = 0; nt < 10; ++nt)
        #pragma unroll
        for (int par = 0; par < 2; ++par) {
            int col = wn * 80 + nt * 8 + 2 * t + par;
            float bv = (col < HDIM) ? b2[col] : 0.f;
            #pragma unroll
            for (int mi = 0; mi < 2; ++mi)
                #pragma unroll
                for (int h8 = 0; h8 < 2; ++h8)
                    acc[mi][nt][h8 * 2 + par] = bv;
        }
    __syncthreads();

    // ======== Stage 2: acc += relu(h1) @ W2 (fp16, K=160) ==================
    for (int kt2 = 0; kt2 < 3; ++kt2) {
        if (kt2 > 0) {
            const char* src = (const char*)(g_W2hi + kt2 * TILE_W_HALVES);
            for (int x = tid; x < TILE_B_U4; x += NTHR)
                cp16(sb + SB2 + x * 16, src + x * 16);
            CP_COMMIT();
            CP_WAIT0();
            __syncthreads();
        }
        const uint32_t aB2 = sb + kt2 * 9216;
        const int nks = (kt2 == 2) ? 2 : 4;
        for (int ks = 0; ks < nks; ++ks) {
            uint32_t af0[4], af1[4];
            ldsm4(af0, aB2 + aOff[0] + ks * 32);
            ldsm4(af1, aB2 + aOff[1] + ks * 32);
            #pragma unroll
            for (int ntp = 0; ntp < 5; ++ntp) {
                uint32_t bf[4];
                ldsm4(bf, sb + SB2 + bOff[ntp] + ks * 32);
                mma16816(acc[0][2 * ntp],     af0[0], af0[1], af0[2], af0[3], bf[0], bf[1]);
                mma16816(acc[1][2 * ntp],     af1[0], af1[1], af1[2], af1[3], bf[0], bf[1]);
                if (ntp < 4 || !trim) {
                    mma16816(acc[0][2 * ntp + 1], af0[0], af0[1], af0[2], af0[3], bf[2], bf[3]);
                    mma16816(acc[1][2 * ntp + 1], af1[0], af1[1], af1[2], af1[3], bf[2], bf[3]);
                }
            }
        }
        __syncthreads();
    }

    // =================== Epilogue: relu(acc) @ W3, reduce ==================
    float rsum[2][2] = {{0.f, 0.f}, {0.f, 0.f}};
    #pragma unroll
    for (int nt = 0; nt < 10; ++nt)
        #pragma unroll
        for (int par = 0; par < 2; ++par) {
            int col = wn * 80 + nt * 8 + 2 * t + par;
            float w3 = (col < HDIM) ? W3[col] : 0.f;
            #pragma unroll
            for (int mi = 0; mi < 2; ++mi)
                #pragma unroll
                for (int h8 = 0; h8 < 2; ++h8)
                    rsum[mi][h8] += fmaxf(acc[mi][nt][h8 * 2 + par], 0.f) * w3;
        }
    #pragma unroll
    for (int mi = 0; mi < 2; ++mi)
        #pragma unroll
        for (int h8 = 0; h8 < 2; ++h8) {
            float v = rsum[mi][h8];
            v += __shfl_xor_sync(0xffffffffu, v, 1);
            v += __shfl_xor_sync(0xffffffffu, v, 2);
            rsum[mi][h8] = v;
        }

    float* sred = (float*)(smem + SRED);
    if (wn == 0 && t == 0) {
        #pragma unroll
        for (int mi = 0; mi < 2; ++mi)
            #pragma unroll
            for (int h8 = 0; h8 < 2; ++h8)
                sred[wm * 32 + mi * 16 + gq + h8 * 8] = rsum[mi][h8];
    }
    __syncthreads();
    if (wn == 1 && t == 0) {
        float smi = sm[i];
        float bb3 = b3[0];
        #pragma unroll
        for (int mi = 0; mi < 2; ++mi)
            #pragma unroll
            for (int h8 = 0; h8 < 2; ++h8) {
                int p = wm * 32 + mi * 16 + gq + h8 * 8;
                int k = k0 + p;
                int j = i - WWIN + k;
                float tot = rsum[mi][h8] + sred[p];
                if (k < WWIN) {
                    float val = 0.f;
                    if (j >= 0) val = tot + bb3 + smi + sm[j];
                    out[(size_t)i * OUTW + k] = val;
                } else if (k == WWIN) {
                    out[(size_t)i * OUTW + k] = 0.f;   // epsilon column
                }
            }
    }
}

// ---------------------------------------------------------------------------
extern "C" void kernel_launch(void* const* d_in, const int* in_sizes, int n_in,
                              void* d_out, int out_size)
{
    const float* g  = (const float*)d_in[0];
    const float* sm = (const float*)d_in[1];
    const float* W1 = (const float*)d_in[2];
    const float* b1 = (const float*)d_in[3];
    const float* W2 = (const float*)d_in[4];
    const float* b2 = (const float*)d_in[5];
    const float* W3 = (const float*)d_in[6];
    const float* b3 = (const float*)d_in[7];
    float* out = (float*)d_out;

    cudaFuncSetAttribute(pair_mma_kernel,
                         cudaFuncAttributeMaxDynamicSharedMemorySize, SMEM_TOTAL);

    precompute_all<<<267, 640>>>(g, W1, b1, W2);

    dim3 grid(4, NN);
    pair_mma_kernel<<<grid, NTHR, SMEM_TOTAL>>>(sm, b2, W3, b3, out);
}

// round 10
// speedup vs baseline: 8.3518x; 1.1231x over previous
#include <cuda_runtime.h>
#include <cuda_fp16.h>
#include <cstdint>

#define NN    1024
#define DDIM  512
#define HDIM  150
#define HP    160
#define WWIN  250
#define OUTW  251
#define NTHR  128
#define MT    64

// ---- dynamic SMEM byte offsets (main kernel) ----
// Stage1: A=0..9216, B buffers: SB0=9216..31104, SB1=31104..52992
// Parity: bB(kt) = (kt&1) ? SB0 : SB1  (kt=7 -> SB0, frees SB1 for W2 prefetch)
// Stage2: h1 tiles at 0 / 9216 / 18432 ; W2 tile at SB2=31104
#define SA    0
#define SB0   9216
#define SB1   31104
#define SB2   31104
#define SRED  52992
#define SMEM_TOTAL 53248

#define BROWS 152
#define TILE_B_BYTES (BROWS * 144)      // 21888
#define TILE_B_U4    (TILE_B_BYTES/16)  // 1368
#define TILE_W_HALVES (BROWS * 72)      // 10944

// ---------------------------------------------------------------------------
// Device scratch
// ---------------------------------------------------------------------------
__device__ float g_giT[NN * HP];      // g@W1a + b1, [i][h], zero pad h>=150
__device__ float g_gjT_T[HP * NN];    // (g@W1b)^T, [h][i], zero pad
__device__ __align__(16) __half g_h[NN * DDIM];   // fp16 copy of g
__device__ __align__(16) __half g_W1hi[8 * TILE_W_HALVES];
__device__ __align__(16) __half g_W2hi[3 * TILE_W_HALVES];

// ---------------------------------------------------------------------------
// Helpers
// ---------------------------------------------------------------------------
__device__ __forceinline__ uint32_t smem_u32(const void* p) {
    uint32_t a;
    asm("{ .reg .u64 t; cvta.to.shared.u64 t, %1; cvt.u32.u64 %0, t; }"
        : "=r"(a) : "l"(p));
    return a;
}

__device__ __forceinline__ void cp16(uint32_t s, const void* g) {
    asm volatile("{\n\t.reg .u64 gp;\n\tcvta.to.global.u64 gp, %1;\n\t"
                 "cp.async.cg.shared.global [%0], [gp], 16;\n\t}"
                 :: "r"(s), "l"(g) : "memory");
}
#define CP_COMMIT() asm volatile("cp.async.commit_group;" ::: "memory")
#define CP_WAIT0()  asm volatile("cp.async.wait_group 0;" ::: "memory")

__device__ __forceinline__ void ldsm4(uint32_t* r, uint32_t addr) {
    asm volatile("ldmatrix.sync.aligned.m8n8.x4.shared.b16 {%0,%1,%2,%3}, [%4];"
        : "=r"(r[0]), "=r"(r[1]), "=r"(r[2]), "=r"(r[3]) : "r"(addr));
}

__device__ __forceinline__ void mma16816(float* c,
    uint32_t a0, uint32_t a1, uint32_t a2, uint32_t a3,
    uint32_t b0, uint32_t b1)
{
    asm volatile(
        "mma.sync.aligned.m16n8k16.row.col.f32.f16.f16.f32 "
        "{%0,%1,%2,%3}, {%4,%5,%6,%7}, {%8,%9}, {%0,%1,%2,%3};"
        : "+f"(c[0]), "+f"(c[1]), "+f"(c[2]), "+f"(c[3])
        : "r"(a0), "r"(a1), "r"(a2), "r"(a3), "r"(b0), "r"(b1));
}

__device__ __forceinline__ uint4 hmul_u4(uint4 x, uint4 y) {
    __half2* xa = (__half2*)&x;
    __half2* ya = (__half2*)&y;
    uint4 r;
    __half2* ra = (__half2*)&r;
    ra[0] = __hmul2(xa[0], ya[0]);
    ra[1] = __hmul2(xa[1], ya[1]);
    ra[2] = __hmul2(xa[2], ya[2]);
    ra[3] = __hmul2(xa[3], ya[3]);
    return r;
}

// ---------------------------------------------------------------------------
// Merged precompute. Blocks 0..255: giT/gjT_T/g_h (4 rows each, 640 thr,
// h = tid%160, ks = tid/160 4-way K-split + SMEM reduce).
// Blocks 256..266: fp16 weight B-tiles (W1c: 8 tiles, W2: 3 tiles).
// ---------------------------------------------------------------------------
__global__ void __launch_bounds__(640) precompute_all(
    const float* __restrict__ g, const float* __restrict__ W1,
    const float* __restrict__ b1, const float* __restrict__ W2)
{
    const int tid = threadIdx.x;

    if (blockIdx.x >= 256) {
        // ---- weight split path ----
        const int bt = blockIdx.x - 256;
        const float* W1c = W1 + 2 * DDIM * HDIM;
        if (bt < 8) {
            __half* dhi = g_W1hi + bt * TILE_W_HALVES;
            for (int idx = tid; idx < BROWS * 64; idx += 640) {
                int n = idx >> 6, k = idx & 63;
                int d = bt * 64 + k;
                float val = (n < HDIM) ? W1c[d * HDIM + n] : 0.f;
                dhi[n * 72 + k] = __float2half_rn(val);
            }
        } else {
            const int kt = bt - 8;
            __half* dhi = g_W2hi + kt * TILE_W_HALVES;
            for (int idx = tid; idx < BROWS * 64; idx += 640) {
                int n = idx >> 6, k = idx & 63;
                int kg = kt * 64 + k;
                float val = (kg < HDIM && n < HDIM) ? W2[kg * HDIM + n] : 0.f;
                dhi[n * 72 + k] = __float2half_rn(val);
            }
        }
        return;
    }

    // ---- giT / gjT path (4 rows per block) ----
    __shared__ float gs[4 * DDIM];
    __shared__ float red[3 * 160 * 8];
    const int i0 = blockIdx.x * 4;
    {
        const float4* src = (const float4*)(g + i0 * DDIM);
        float4* dst = (float4*)gs;
        for (int x = tid; x < (4 * DDIM) / 4; x += 640) dst[x] = src[x];
    }
    __syncthreads();
    // fp16 copy of these 4 rows
    for (int x = tid; x < 4 * DDIM; x += 640)
        g_h[i0 * DDIM + x] = __float2half_rn(gs[x]);

    const int h  = tid % 160;
    const int ks = tid / 160;
    const bool hv = (h < HDIM);
    const int hc = hv ? h : 0;
    float acc1[4], acc2[4];
    float bb = (hv && ks == 0) ? b1[h] : 0.f;
    #pragma unroll
    for (int q = 0; q < 4; ++q) { acc1[q] = bb; acc2[q] = 0.f; }
    const float* W1a = W1 + hc;
    const float* W1b = W1 + DDIM * HDIM + hc;
    const int d0b = ks * 128;
    for (int d0 = d0b; d0 < d0b + 128; d0 += 8) {
        float w1r[8], w2r[8];
        #pragma unroll
        for (int u = 0; u < 8; ++u) {
            w1r[u] = W1a[(d0 + u) * HDIM];
            w2r[u] = W1b[(d0 + u) * HDIM];
        }
        if (!hv) {
            #pragma unroll
            for (int u = 0; u < 8; ++u) { w1r[u] = 0.f; w2r[u] = 0.f; }
        }
        #pragma unroll
        for (int q = 0; q < 4; ++q) {
            const float* gq = gs + q * DDIM + d0;
            float4 ga = *(const float4*)gq;
            float4 gb = *(const float4*)(gq + 4);
            acc1[q] += ga.x * w1r[0] + ga.y * w1r[1] + ga.z * w1r[2] + ga.w * w1r[3]
                     + gb.x * w1r[4] + gb.y * w1r[5] + gb.z * w1r[6] + gb.w * w1r[7];
            acc2[q] += ga.x * w2r[0] + ga.y * w2r[1] + ga.z * w2r[2] + ga.w * w2r[3]
                     + gb.x * w2r[4] + gb.y * w2r[5] + gb.z * w2r[6] + gb.w * w2r[7];
        }
    }
    if (ks > 0) {
        float* r = red + ((ks - 1) * 160 + h) * 8;
        #pragma unroll
        for (int q = 0; q < 4; ++q) { r[q] = acc1[q]; r[4 + q] = acc2[q]; }
    }
    __syncthreads();
    if (ks == 0) {
        #pragma unroll
        for (int s = 0; s < 3; ++s) {
            const float* r = red + (s * 160 + h) * 8;
            #pragma unroll
            for (int q = 0; q < 4; ++q) { acc1[q] += r[q]; acc2[q] += r[4 + q]; }
        }
        #pragma unroll
        for (int q = 0; q < 4; ++q) {
            g_giT[(i0 + q) * HP + h]   = acc1[q];
            g_gjT_T[h * NN + (i0 + q)] = acc2[q];
        }
    }
}

// ---------------------------------------------------------------------------
// Main kernel. CTA = (i, 64 pairs). grid (4, 1024). 4 warps: wm=wid&1 (M 32),
// wn=wid>>1 (N 80). A single-buffered, B double-buffered, N=152.
// A-prep coalesced: thread -> (row = rd*16 + tid>>3, 16B chunk = tid&7).
// ---------------------------------------------------------------------------
__global__ void __launch_bounds__(NTHR, 4) pair_mma_kernel(
    const float* __restrict__ sm, const float* __restrict__ b2,
    const float* __restrict__ W3, const float* __restrict__ b3,
    float* __restrict__ out)
{
    extern __shared__ char smem[];
    const uint32_t sb = smem_u32(smem);
    const int tid = threadIdx.x;
    const int i  = blockIdx.y;
    const int k0 = blockIdx.x * MT;

    // ---- early exit: whole CTA out of window ----
    if (i - WWIN + k0 + (MT - 1) < 0) {
        if (tid < MT) out[(size_t)i * OUTW + k0 + tid] = 0.f;
        return;
    }

    const int wid = tid >> 5, lid = tid & 31;
    const int wm = wid & 1, wn = wid >> 1;
    const int gq = lid >> 2, t = lid & 3;
    const bool trim = (wn == 1);   // this warp owns cols 80..159; tile19 dead

    int jrow[2][2];
    #pragma unroll
    for (int mi = 0; mi < 2; ++mi)
        #pragma unroll
        for (int h8 = 0; h8 < 2; ++h8) {
            int p = wm * 32 + mi * 16 + gq + h8 * 8;
            int j = i - WWIN + k0 + p;
            jrow[mi][h8] = min(max(j, 0), NN - 1);
        }

    // ---- accumulators, init with bias terms giT[i][col] + gjT[col][j] ----
    float acc[2][10][4];
    {
        const float* giR = g_giT + i * HP;
        #pragma unroll
        for (int nt = 0; nt < 10; ++nt)
            #pragma unroll
            for (int par = 0; par < 2; ++par) {
                int col = wn * 80 + nt * 8 + 2 * t + par;
                float gic = giR[col];
                const float* gjc = g_gjT_T + col * NN;
                #pragma unroll
                for (int mi = 0; mi < 2; ++mi)
                    #pragma unroll
                    for (int h8 = 0; h8 < 2; ++h8)
                        acc[mi][nt][h8 * 2 + par] = gic + gjc[jrow[mi][h8]];
            }
    }

    // ---- ldmatrix lane offsets ----
    const int mq = lid >> 3, rr = lid & 7;
    uint32_t aOff[2], bOff[5];
    #pragma unroll
    for (int mi = 0; mi < 2; ++mi)
        aOff[mi] = (uint32_t)((wm * 32 + mi * 16 + (mq & 1) * 8 + rr) * 144 + (mq >> 1) * 16);
    #pragma unroll
    for (int ntp = 0; ntp < 5; ++ntp) {
        int rowb = wn * 80 + (ntp * 2 + (mq >> 1)) * 8 + rr;
        if (rowb > 151) rowb = 151;           // clamp dead tile-19 rows (values unused)
        bOff[ntp] = (uint32_t)(rowb * 144 + (mq & 1) * 16);
    }

    // ---- A-prep identity (coalesced): 4 rounds of 16 rows x 8 chunks ----
    const int c8 = tid & 7;            // 16B chunk within 128B k-slab
    const int rA = tid >> 3;           // 0..15
    const __half* giBase = g_h + (size_t)i * DDIM;
    int jr[4];
    #pragma unroll
    for (int rd = 0; rd < 4; ++rd) {
        int p = rd * 16 + rA;
        jr[rd] = min(max(i - WWIN + k0 + p, 0), NN - 1);
    }

    // =================== Stage 1: acc += (gi*gj) @ W1c (fp16) ==============
    {
        const char* src = (const char*)g_W1hi;       // kt=0 -> SB1 (parity: even->SB1)
        for (int x = tid; x < TILE_B_U4; x += NTHR)
            cp16(sb + SB1 + x * 16, src + x * 16);
        CP_COMMIT();
        // A-prep kt=0
        const uint4 gi16 = ((const uint4*)(giBase + 0))[c8];
        #pragma unroll
        for (int rd = 0; rd < 4; ++rd) {
            uint4 gj16 = ((const uint4*)(g_h + (size_t)jr[rd] * DDIM))[c8];
            *(uint4*)(smem + SA + (rd * 16 + rA) * 144 + c8 * 16) = hmul_u4(gi16, gj16);
        }
        CP_WAIT0();
        __syncthreads();
    }

    for (int kt = 0; kt < 8; ++kt) {
        if (kt < 7) {
            const char* src = (const char*)(g_W1hi + (kt + 1) * TILE_W_HALVES);
            uint32_t dstB = sb + (((kt + 1) & 1) ? SB0 : SB1);
            for (int x = tid; x < TILE_B_U4; x += NTHR)
                cp16(dstB + x * 16, src + x * 16);
            CP_COMMIT();
        } else {
            // kt=7 consumes SB0; SB1 region is dead -> prefetch W2 tile 0 there
            const char* src = (const char*)g_W2hi;
            for (int x = tid; x < TILE_B_U4; x += NTHR)
                cp16(sb + SB2 + x * 16, src + x * 16);
            CP_COMMIT();
        }

        const uint32_t bB = sb + ((kt & 1) ? SB0 : SB1);
        #pragma unroll
        for (int ks = 0; ks < 4; ++ks) {
            uint32_t ah0[4], ah1[4];
            ldsm4(ah0, sb + SA + aOff[0] + ks * 32);
            ldsm4(ah1, sb + SA + aOff[1] + ks * 32);
            #pragma unroll
            for (int ntp = 0; ntp < 5; ++ntp) {
                uint32_t bf[4];
                ldsm4(bf, bB + bOff[ntp] + ks * 32);
                mma16816(acc[0][2 * ntp],     ah0[0], ah0[1], ah0[2], ah0[3], bf[0], bf[1]);
                mma16816(acc[1][2 * ntp],     ah1[0], ah1[1], ah1[2], ah1[3], bf[0], bf[1]);
                if (ntp < 4 || !trim) {
                    mma16816(acc[0][2 * ntp + 1], ah0[0], ah0[1], ah0[2], ah0[3], bf[2], bf[3]);
                    mma16816(acc[1][2 * ntp + 1], ah1[0], ah1[1], ah1[2], ah1[3], bf[2], bf[3]);
                }
            }
        }
        __syncthreads();             // A + B(kt) consumed by all warps

        if (kt < 7) {
            const uint4 gi16 = ((const uint4*)(giBase + (kt + 1) * 64))[c8];
            #pragma unroll
            for (int rd = 0; rd < 4; ++rd) {
                uint4 gj16 = ((const uint4*)(g_h + (size_t)jr[rd] * DDIM + (kt + 1) * 64))[c8];
                *(uint4*)(smem + SA + (rd * 16 + rA) * 144 + c8 * 16) = hmul_u4(gi16, gj16);
            }
        }
        CP_WAIT0();
        __syncthreads();
    }

    // ============ h1 = relu(acc) -> SMEM (single fp16, 3 k-tiles) ==========
    {
        #pragma unroll
        for (int mi = 0; mi < 2; ++mi)
            #pragma unroll
            for (int h8 = 0; h8 < 2; ++h8) {
                int row = wm * 32 + mi * 16 + gq + h8 * 8;
                #pragma unroll
                for (int nt = 0; nt < 10; ++nt) {
                    int col = wn * 80 + nt * 8 + 2 * t;
                    float v0 = fmaxf(acc[mi][nt][h8 * 2 + 0], 0.f);
                    float v1 = fmaxf(acc[mi][nt][h8 * 2 + 1], 0.f);
                    __half2 h = __float22half2_rn(make_float2(v0, v1));
                    int tile = col >> 6;
                    uint32_t off = (uint32_t)(tile * 9216 + row * 144 + (col & 63) * 2);
                    *(uint32_t*)(smem + off) = *(uint32_t*)&h;
                }
            }
    }

    // ---- re-init acc with b2 for stage 2 ----
    #pragma unroll
    for (int nt = 0; nt < 10; ++nt)
        #pragma unroll
        for (int par = 0; par < 2; ++par) {
            int col = wn * 80 + nt * 8 + 2 * t + par;
            float bv = (col < HDIM) ? b2[col] : 0.f;
            #pragma unroll
            for (int mi = 0; mi < 2; ++mi)
                #pragma unroll
                for (int h8 = 0; h8 < 2; ++h8)
                    acc[mi][nt][h8 * 2 + par] = bv;
        }
    __syncthreads();

    // ======== Stage 2: acc += relu(h1) @ W2 (fp16, K=160) ==================
    for (int kt2 = 0; kt2 < 3; ++kt2) {
        if (kt2 > 0) {
            const char* src = (const char*)(g_W2hi + kt2 * TILE_W_HALVES);
            for (int x = tid; x < TILE_B_U4; x += NTHR)
                cp16(sb + SB2 + x * 16, src + x * 16);
            CP_COMMIT();
            CP_WAIT0();
            __syncthreads();
        }
        const uint32_t aB2 = sb + kt2 * 9216;
        const int nks = (kt2 == 2) ? 2 : 4;
        for (int ks = 0; ks < nks; ++ks) {
            uint32_t af0[4], af1[4];
            ldsm4(af0, aB2 + aOff[0] + ks * 32);
            ldsm4(af1, aB2 + aOff[1] + ks * 32);
            #pragma unroll
            for (int ntp = 0; ntp < 5; ++ntp) {
                uint32_t bf[4];
                ldsm4(bf, sb + SB2 + bOff[ntp] + ks * 32);
                mma16816(acc[0][2 * ntp],     af0[0], af0[1], af0[2], af0[3], bf[0], bf[1]);
                mma16816(acc[1][2 * ntp],     af1[0], af1[1], af1[2], af1[3], bf[0], bf[1]);
                if (ntp < 4 || !trim) {
                    mma16816(acc[0][2 * ntp + 1], af0[0], af0[1], af0[2], af0[3], bf[2], bf[3]);
                    mma16816(acc[1][2 * ntp + 1], af1[0], af1[1], af1[2], af1[3], bf[2], bf[3]);
                }
            }
        }
        __syncthreads();
    }

    // =================== Epilogue: relu(acc) @ W3, reduce ==================
    float rsum[2][2] = {{0.f, 0.f}, {0.f, 0.f}};
    #pragma unroll
    for (int nt = 0; nt < 10; ++nt)
        #pragma unroll
        for (int par = 0; par < 2; ++par) {
            int col = wn * 80 + nt * 8 + 2 * t + par;
            float w3 = (col < HDIM) ? W3[col] : 0.f;
            #pragma unroll
            for (int mi = 0; mi < 2; ++mi)
                #pragma unroll
                for (int h8 = 0; h8 < 2; ++h8)
                    rsum[mi][h8] += fmaxf(acc[mi][nt][h8 * 2 + par], 0.f) * w3;
        }
    #pragma unroll
    for (int mi = 0; mi < 2; ++mi)
        #pragma unroll
        for (int h8 = 0; h8 < 2; ++h8) {
            float v = rsum[mi][h8];
            v += __shfl_xor_sync(0xffffffffu, v, 1);
            v += __shfl_xor_sync(0xffffffffu, v, 2);
            rsum[mi][h8] = v;
        }

    float* sred = (float*)(smem + SRED);
    if (wn == 0 && t == 0) {
        #pragma unroll
        for (int mi = 0; mi < 2; ++mi)
            #pragma unroll
            for (int h8 = 0; h8 < 2; ++h8)
                sred[wm * 32 + mi * 16 + gq + h8 * 8] = rsum[mi][h8];
    }
    __syncthreads();
    if (wn == 1 && t == 0) {
        float smi = sm[i];
        float bb3 = b3[0];
        #pragma unroll
        for (int mi = 0; mi < 2; ++mi)
            #pragma unroll
            for (int h8 = 0; h8 < 2; ++h8) {
                int p = wm * 32 + mi * 16 + gq + h8 * 8;
                int k = k0 + p;
                int j = i - WWIN + k;
                float tot = rsum[mi][h8] + sred[p];
                if (k < WWIN) {
                    float val = 0.f;
                    if (j >= 0) val = tot + bb3 + smi + sm[j];
                    out[(size_t)i * OUTW + k] = val;
                } else if (k == WWIN) {
                    out[(size_t)i * OUTW + k] = 0.f;   // epsilon column
                }
            }
    }
}

// ---------------------------------------------------------------------------
extern "C" void kernel_launch(void* const* d_in, const int* in_sizes, int n_in,
                              void* d_out, int out_size)
{
    const float* g  = (const float*)d_in[0];
    const float* sm = (const float*)d_in[1];
    const float* W1 = (const float*)d_in[2];
    const float* b1 = (const float*)d_in[3];
    const float* W2 = (const float*)d_in[4];
    const float* b2 = (const float*)d_in[5];
    const float* W3 = (const float*)d_in[6];
    const float* b3 = (const float*)d_in[7];
    float* out = (float*)d_out;

    cudaFuncSetAttribute(pair_mma_kernel,
                         cudaFuncAttributeMaxDynamicSharedMemorySize, SMEM_TOTAL);

    precompute_all<<<267, 640>>>(g, W1, b1, W2);

    dim3 grid(4, NN);
    pair_mma_kernel<<<grid, NTHR, SMEM_TOTAL>>>(sm, b2, W3, b3, out);
}